// round 4
// baseline (speedup 1.0000x reference)
#include <cuda_runtime.h>
#include <math.h>

// ---------------- problem constants ----------------
#define BATCH 2
#define SEQ   2048
#define EMBED 1024
#define HEADS 16
#define HD    64
#define FF    4096
#define MTOK  (BATCH*SEQ)          // 4096 token rows
#define QKVN  (3*EMBED)            // 3072

// ---------------- device scratch (no allocs allowed) ----------------
__device__ float g_normed [(size_t)MTOK*EMBED];
__device__ float g_wqkv   [(size_t)EMBED*QKVN];
__device__ float g_qkv    [(size_t)MTOK*QKVN];
__device__ float g_scores [(size_t)BATCH*HEADS*SEQ*SEQ];   // 512 MB
__device__ float g_attn   [(size_t)MTOK*EMBED];
__device__ float g_x2     [(size_t)MTOK*EMBED];
__device__ float g_normed2[(size_t)MTOK*EMBED];
__device__ float g_ff1    [(size_t)MTOK*FF];

// ---------------- LayerNorm: one block per row of 1024 ----------------
__global__ void ln_kernel(const float* __restrict__ x,
                          const float* __restrict__ gam,
                          const float* __restrict__ bet,
                          float* __restrict__ out) {
    int row = blockIdx.x;
    int t = threadIdx.x;                       // 256 threads, 4 floats each
    const float4* xr = (const float4*)(x + (size_t)row*EMBED);
    float4 v = xr[t];
    float s  = v.x + v.y + v.z + v.w;
    float ss = v.x*v.x + v.y*v.y + v.z*v.z + v.w*v.w;
    #pragma unroll
    for (int o = 16; o; o >>= 1) {
        s  += __shfl_xor_sync(0xffffffffu, s,  o);
        ss += __shfl_xor_sync(0xffffffffu, ss, o);
    }
    __shared__ float shs[8], shs2[8];
    int w = t >> 5;
    if ((t & 31) == 0) { shs[w] = s; shs2[w] = ss; }
    __syncthreads();
    float tot = 0.f, tot2 = 0.f;
    #pragma unroll
    for (int i = 0; i < 8; i++) { tot += shs[i]; tot2 += shs2[i]; }
    float mu  = tot * (1.f/EMBED);
    float var = tot2 * (1.f/EMBED) - mu*mu;
    float rs  = rsqrtf(var + 1e-5f);
    float4 gv = ((const float4*)gam)[t];
    float4 bv = ((const float4*)bet)[t];
    float4 o;
    o.x = (v.x - mu)*rs*gv.x + bv.x;
    o.y = (v.y - mu)*rs*gv.y + bv.y;
    o.z = (v.z - mu)*rs*gv.z + bv.z;
    o.w = (v.w - mu)*rs*gv.w + bv.w;
    ((float4*)(out + (size_t)row*EMBED))[t] = o;
}

// ---------------- repack Wqkv (48,1024,64) -> (1024, 3072) ----------------
__global__ void repack_wqkv(const float* __restrict__ w, float* __restrict__ out) {
    int idx = blockIdx.x * blockDim.x + threadIdx.x;    // over 1024*3072
    int n = idx % QKVN;
    int d = idx / QKVN;
    int g = n >> 6;         // group 0..47
    int h = n & 63;
    out[idx] = w[((size_t)g*EMBED + d)*HD + h];
}

// ---------------- softmax: one block per row of 2048 ----------------
__global__ void softmax_kernel(float* __restrict__ p) {
    size_t row = blockIdx.x;
    float4* pr = (float4*)(p + row*(size_t)SEQ);
    int t = threadIdx.x;                       // 256 threads, 8 floats each
    float4 a = pr[t];
    float4 b = pr[t + 256];
    float mx = fmaxf(fmaxf(fmaxf(a.x,a.y),fmaxf(a.z,a.w)),
                     fmaxf(fmaxf(b.x,b.y),fmaxf(b.z,b.w)));
    #pragma unroll
    for (int o = 16; o; o >>= 1) mx = fmaxf(mx, __shfl_xor_sync(0xffffffffu, mx, o));
    __shared__ float sh[8];
    int w = t >> 5;
    if ((t & 31) == 0) sh[w] = mx;
    __syncthreads();
    #pragma unroll
    for (int i = 0; i < 8; i++) mx = fmaxf(mx, sh[i]);
    __syncthreads();
    a.x = __expf(a.x - mx); a.y = __expf(a.y - mx);
    a.z = __expf(a.z - mx); a.w = __expf(a.w - mx);
    b.x = __expf(b.x - mx); b.y = __expf(b.y - mx);
    b.z = __expf(b.z - mx); b.w = __expf(b.w - mx);
    float s = a.x+a.y+a.z+a.w + b.x+b.y+b.z+b.w;
    #pragma unroll
    for (int o = 16; o; o >>= 1) s += __shfl_xor_sync(0xffffffffu, s, o);
    if ((t & 31) == 0) sh[w] = s;
    __syncthreads();
    float tot = 0.f;
    #pragma unroll
    for (int i = 0; i < 8; i++) tot += sh[i];
    float inv = 1.f / tot;
    a.x *= inv; a.y *= inv; a.z *= inv; a.w *= inv;
    b.x *= inv; b.y *= inv; b.z *= inv; b.w *= inv;
    pr[t] = a;
    pr[t + 256] = b;
}

// ---------------- generic tiled SGEMM ----------------
// C[m,n] = alpha * sum_k A[m,k] * (TB ? B[n,k] : B[k,n])  (+bias)(+resid)(relu)
// Batched over blockIdx.z with split strides: z = zb*16 + zh.
template<int BM,int BN,int BK,int TM,int TN,bool TB,bool RELU,bool RES>
__global__ __launch_bounds__((BM/TM)*(BN/TN))
void gemm_kernel(const float* __restrict__ A, const float* __restrict__ B,
                 const float* __restrict__ bias, const float* __restrict__ resid,
                 float* __restrict__ C,
                 int K, int lda, int ldb, int ldc, int ldres,
                 long sAb, long sAh, long sBb, long sBh, long sCb, long sCh,
                 float alpha)
{
    constexpr int THREADS = (BM/TM)*(BN/TN);
    int z  = blockIdx.z;
    int zb = z >> 4, zh = z & 15;
    A += (size_t)zb*sAb + (size_t)zh*sAh;
    B += (size_t)zb*sBb + (size_t)zh*sBh;
    C += (size_t)zb*sCb + (size_t)zh*sCh;

    __shared__ __align__(16) float As[BK][BM];
    __shared__ __align__(16) float Bs[BK][BN];

    int tid = threadIdx.x;
    int tn = tid % (BN/TN);
    int tm = tid / (BN/TN);
    int row0 = blockIdx.y * BM;
    int col0 = blockIdx.x * BN;

    float acc[TM][TN] = {};

    for (int k0 = 0; k0 < K; k0 += BK) {
        // stage A (transpose into As[k][m])
        #pragma unroll
        for (int i = tid*4; i < BM*BK; i += THREADS*4) {
            int m = i / BK, kk = i % BK;
            const float4 v = *(const float4*)(A + (size_t)(row0+m)*lda + k0 + kk);
            As[kk+0][m] = v.x; As[kk+1][m] = v.y;
            As[kk+2][m] = v.z; As[kk+3][m] = v.w;
        }
        // stage B
        if (TB) {
            #pragma unroll
            for (int i = tid*4; i < BK*BN; i += THREADS*4) {
                int n = i / BK, kk = i % BK;
                const float4 v = *(const float4*)(B + (size_t)(col0+n)*ldb + k0 + kk);
                Bs[kk+0][n] = v.x; Bs[kk+1][n] = v.y;
                Bs[kk+2][n] = v.z; Bs[kk+3][n] = v.w;
            }
        } else {
            #pragma unroll
            for (int i = tid*4; i < BK*BN; i += THREADS*4) {
                int kk = i / BN, n = i % BN;
                *(float4*)&Bs[kk][n] = *(const float4*)(B + (size_t)(k0+kk)*ldb + col0 + n);
            }
        }
        __syncthreads();

        #pragma unroll
        for (int kk = 0; kk < BK; kk++) {
            float ra[TM], rb[TN];
            #pragma unroll
            for (int i = 0; i < TM; i += 4)
                *(float4*)&ra[i] = *(const float4*)&As[kk][tm*TM + i];
            #pragma unroll
            for (int j = 0; j < TN; j += 4)
                *(float4*)&rb[j] = *(const float4*)&Bs[kk][tn*TN + j];
            #pragma unroll
            for (int i = 0; i < TM; i++)
                #pragma unroll
                for (int j = 0; j < TN; j++)
                    acc[i][j] = fmaf(ra[i], rb[j], acc[i][j]);
        }
        __syncthreads();
    }

    #pragma unroll
    for (int i = 0; i < TM; i++) {
        int m = row0 + tm*TM + i;
        #pragma unroll
        for (int j = 0; j < TN; j++) {
            int n = col0 + tn*TN + j;
            float v = acc[i][j] * alpha;
            if (bias) v += bias[n];
            if (RES)  v += resid[(size_t)m*ldres + n];
            if (RELU) v = fmaxf(v, 0.f);
            C[(size_t)m*ldc + n] = v;
        }
    }
}

// ---------------- launch ----------------
extern "C" void kernel_launch(void* const* d_in, const int* in_sizes, int n_in,
                              void* d_out, int out_size) {
    const float* x    = (const float*)d_in[0];
    const float* Wqkv = (const float*)d_in[1];
    const float* bqkv = (const float*)d_in[2];   // (48,64) contiguous == [3072]
    const float* Wo   = (const float*)d_in[3];
    const float* bo   = (const float*)d_in[4];
    const float* W1   = (const float*)d_in[5];
    const float* b1   = (const float*)d_in[6];
    const float* W2   = (const float*)d_in[7];
    const float* b2   = (const float*)d_in[8];
    const float* g1   = (const float*)d_in[9];
    const float* be1  = (const float*)d_in[10];
    const float* g2   = (const float*)d_in[11];
    const float* be2  = (const float*)d_in[12];
    float* out = (float*)d_out;

    float *normed, *wq, *qkv, *scores, *attn, *x2, *normed2, *ff1;
    cudaGetSymbolAddress((void**)&normed,  g_normed);
    cudaGetSymbolAddress((void**)&wq,      g_wqkv);
    cudaGetSymbolAddress((void**)&qkv,     g_qkv);
    cudaGetSymbolAddress((void**)&scores,  g_scores);
    cudaGetSymbolAddress((void**)&attn,    g_attn);
    cudaGetSymbolAddress((void**)&x2,      g_x2);
    cudaGetSymbolAddress((void**)&normed2, g_normed2);
    cudaGetSymbolAddress((void**)&ff1,     g_ff1);

    // 1. LN1
    ln_kernel<<<MTOK, 256>>>(x, g1, be1, normed);

    // 2. repack Wqkv -> [1024, 3072]
    repack_wqkv<<<(EMBED*QKVN)/256, 256>>>(Wqkv, wq);

    // 3. QKV projection: [4096,1024]@[1024,3072] + bqkv
    gemm_kernel<128,128,8,8,8,false,false,false>
        <<<dim3(QKVN/128, MTOK/128, 1), 256>>>(
        normed, wq, bqkv, nullptr, qkv,
        EMBED, EMBED, QKVN, QKVN, 0,
        0,0,0,0,0,0, 1.f);

    // 4. scores = Q @ K^T / 8  per (b,h): z = b*16+h
    gemm_kernel<128,128,8,8,8,true,false,false>
        <<<dim3(SEQ/128, SEQ/128, BATCH*HEADS), 256>>>(
        qkv /*Q cols*/, qkv + EMBED /*K cols*/, nullptr, nullptr, scores,
        HD, QKVN, QKVN, SEQ, 0,
        (long)SEQ*QKVN, 64,            // A strides (per b, per h)
        (long)SEQ*QKVN, 64,            // B strides
        (long)HEADS*SEQ*SEQ, (long)SEQ*SEQ,  // C strides
        0.125f);

    // 5. softmax over each of 65536 rows
    softmax_kernel<<<BATCH*HEADS*SEQ, 256>>>(scores);

    // 6. attn = P @ V, written directly into [b, s, h*64+d] layout
    gemm_kernel<128,64,8,8,4,false,false,false>
        <<<dim3(1, SEQ/128, BATCH*HEADS), 256>>>(
        scores, qkv + 2*EMBED /*V cols*/, nullptr, nullptr, attn,
        SEQ, SEQ, QKVN, EMBED, 0,
        (long)HEADS*SEQ*SEQ, (long)SEQ*SEQ,
        (long)SEQ*QKVN, 64,
        (long)SEQ*EMBED, 64,
        1.f);

    // 7. O projection + bias + residual(x) -> x2
    gemm_kernel<128,128,8,8,8,false,false,true>
        <<<dim3(EMBED/128, MTOK/128, 1), 256>>>(
        attn, Wo, bo, x, x2,
        EMBED, EMBED, EMBED, EMBED, EMBED,
        0,0,0,0,0,0, 1.f);

    // 8. LN2
    ln_kernel<<<MTOK, 256>>>(x2, g2, be2, normed2);

    // 9. FF1 + bias + relu
    gemm_kernel<128,128,8,8,8,false,true,false>
        <<<dim3(FF/128, MTOK/128, 1), 256>>>(
        normed2, W1, b1, nullptr, ff1,
        EMBED, EMBED, FF, FF, 0,
        0,0,0,0,0,0, 1.f);

    // 10. FF2 + bias + residual(x2) -> out
    gemm_kernel<128,128,8,8,8,false,false,true>
        <<<dim3(EMBED/128, MTOK/128, 1), 256>>>(
        ff1, W2, b2, x2, out,
        FF, FF, EMBED, EMBED, EMBED,
        0,0,0,0,0,0, 1.f);
}

// round 7
// speedup vs baseline: 2.1915x; 2.1915x over previous
#include <cuda_runtime.h>
#include <cuda_bf16.h>
#include <cstdint>
#include <math.h>

// ---------------- problem constants ----------------
#define BATCH 2
#define SEQ   2048
#define EMBED 1024
#define HEADS 16
#define HD    64
#define FF    4096
#define MTOK  (BATCH*SEQ)          // 4096
#define QKVN  (3*EMBED)            // 3072

typedef __nv_bfloat16 bf16;

// ---------------- device scratch ----------------
__device__ __align__(16) float g_normed [(size_t)MTOK*EMBED];
__device__ __align__(16) float g_qkv    [(size_t)MTOK*QKVN];
__device__ __align__(16) float g_scores [(size_t)BATCH*HEADS*SEQ*SEQ];   // 512 MB
__device__ __align__(16) float g_attn   [(size_t)MTOK*EMBED];
__device__ __align__(16) float g_x2     [(size_t)MTOK*EMBED];
__device__ __align__(16) float g_normed2[(size_t)MTOK*EMBED];
__device__ __align__(16) float g_ff1    [(size_t)MTOK*FF];

// bf16 split operand buffers (hi / lo)
__device__ __align__(16) bf16 g_nrm_h  [(size_t)MTOK*EMBED];
__device__ __align__(16) bf16 g_nrm_l  [(size_t)MTOK*EMBED];
__device__ __align__(16) bf16 g_wqkvT_h[(size_t)QKVN*EMBED];
__device__ __align__(16) bf16 g_wqkvT_l[(size_t)QKVN*EMBED];
__device__ __align__(16) bf16 g_q_h    [(size_t)BATCH*HEADS*SEQ*HD];
__device__ __align__(16) bf16 g_q_l    [(size_t)BATCH*HEADS*SEQ*HD];
__device__ __align__(16) bf16 g_k_h    [(size_t)BATCH*HEADS*SEQ*HD];
__device__ __align__(16) bf16 g_k_l    [(size_t)BATCH*HEADS*SEQ*HD];
__device__ __align__(16) bf16 g_vT_h   [(size_t)BATCH*HEADS*HD*SEQ];
__device__ __align__(16) bf16 g_vT_l   [(size_t)BATCH*HEADS*HD*SEQ];
__device__ __align__(16) bf16 g_p_h    [(size_t)BATCH*HEADS*SEQ*SEQ];    // 268MB
__device__ __align__(16) bf16 g_p_l    [(size_t)BATCH*HEADS*SEQ*SEQ];
__device__ __align__(16) bf16 g_attn_h [(size_t)MTOK*EMBED];
__device__ __align__(16) bf16 g_attn_l [(size_t)MTOK*EMBED];
__device__ __align__(16) bf16 g_woT_h  [(size_t)EMBED*EMBED];
__device__ __align__(16) bf16 g_woT_l  [(size_t)EMBED*EMBED];
__device__ __align__(16) bf16 g_n2_h   [(size_t)MTOK*EMBED];
__device__ __align__(16) bf16 g_n2_l   [(size_t)MTOK*EMBED];
__device__ __align__(16) bf16 g_w1T_h  [(size_t)FF*EMBED];
__device__ __align__(16) bf16 g_w1T_l  [(size_t)FF*EMBED];
__device__ __align__(16) bf16 g_ff1_h  [(size_t)MTOK*FF];
__device__ __align__(16) bf16 g_ff1_l  [(size_t)MTOK*FF];
__device__ __align__(16) bf16 g_w2T_h  [(size_t)EMBED*FF];
__device__ __align__(16) bf16 g_w2T_l  [(size_t)EMBED*FF];

// ---------------- PTX helpers (sm_80-level only; NO 'a' features) ----------------
__device__ __forceinline__ uint32_t smem_u32(const void* p) {
    uint32_t a;
    asm("{ .reg .u64 t; cvta.to.shared.u64 t, %1; cvt.u32.u64 %0, t; }" : "=r"(a) : "l"(p));
    return a;
}
#define CP16(dst, src) \
    asm volatile("cp.async.cg.shared.global [%0], [%1], 16;" :: "r"(dst), "l"(src) : "memory")
#define CP_COMMIT() asm volatile("cp.async.commit_group;" ::: "memory")
#define CP_WAIT0()  asm volatile("cp.async.wait_group 0;" ::: "memory")
#define CP_WAIT1()  asm volatile("cp.async.wait_group 1;" ::: "memory")

#define MMA16816(d, a, b0, b1)                                               \
    asm volatile("mma.sync.aligned.m16n8k16.row.col.f32.bf16.bf16.f32 "      \
        "{%0,%1,%2,%3}, {%4,%5,%6,%7}, {%8,%9}, {%0,%1,%2,%3};"              \
        : "+f"((d)[0]), "+f"((d)[1]), "+f"((d)[2]), "+f"((d)[3])             \
        : "r"((a)[0]), "r"((a)[1]), "r"((a)[2]), "r"((a)[3]),                \
          "r"(b0), "r"(b1))

// ---------------- split helper ----------------
__device__ __forceinline__ void split1(float x, bf16& h, bf16& l) {
    h = __float2bfloat16(x);
    l = __float2bfloat16(x - __bfloat162float(h));
}

// ---------------- HMMA bf16-split GEMM ----------------
// C[m,n] = alpha * sum_k (Ah+Al)[m,k]*(Bh+Bl)[n,k]  (+bias)(+resid)(relu)
// A: [M, lda] K-major. B: [N, ldb] K-major. Both hi/lo bf16.
// batch z: A += z*sAz, B += z*sBz, C += (z>>4)*sCb + (z&15)*sCh.
template<int BN, bool BIAS, bool RES, bool RELU>
__global__ __launch_bounds__(256, 1)
void mma_gemm(const bf16* __restrict__ Ah, const bf16* __restrict__ Al,
              const bf16* __restrict__ Bh, const bf16* __restrict__ Bl,
              const float* __restrict__ bias, const float* __restrict__ resid,
              float* __restrict__ C,
              int K, int lda, int ldb, int ldc, int ldres,
              long sAz, long sBz, long sCb, long sCh,
              float alpha)
{
    constexpr int BM = 128, BK = 64;
    constexpr int SROW   = BK + 8;               // 72 halves/row: conflict-free frag LDS
    constexpr int A_TILE = BM * SROW;            // halves
    constexpr int B_TILE = BN * SROW;
    constexpr int STAGE  = 2 * A_TILE + 2 * B_TILE;
    constexpr int NT     = BN / 16;              // n8-tiles per warp (warp covers BN/2)

    extern __shared__ __align__(16) bf16 smem[];
    const uint32_t sbase = smem_u32(smem);
    const int tid = threadIdx.x;

    const int z = blockIdx.z;
    Ah += (size_t)z * sAz;  Al += (size_t)z * sAz;
    Bh += (size_t)z * sBz;  Bl += (size_t)z * sBz;
    C  += (size_t)(z >> 4) * sCb + (size_t)(z & 15) * sCh;

    const int row0 = blockIdx.y * BM;
    const int col0 = blockIdx.x * BN;

    const int wid = tid >> 5, lane = tid & 31;
    const int g = lane >> 2, t = lane & 3;
    const int wrow0 = (wid & 3) * 32;            // warp covers 32 rows (2 m16 tiles)
    const int wcol0 = (wid >> 2) * (BN / 2);     // warp covers BN/2 cols

    float acc[2][NT][4];
    #pragma unroll
    for (int mt = 0; mt < 2; mt++)
        #pragma unroll
        for (int nt = 0; nt < NT; nt++)
            #pragma unroll
            for (int i = 0; i < 4; i++) acc[mt][nt][i] = 0.f;

    // ---- async stage of one BK chunk into buffer b ----
    auto stage = [&](int b, int c) {
        const int k0 = c * BK;
        const uint32_t sb = sbase + (uint32_t)b * STAGE * 2;
        // A: 128 rows x 8 16B-chunks, hi+lo
        for (int i = tid; i < BM * 8; i += 256) {
            int r = i >> 3, q = i & 7;
            uint32_t d = sb + (uint32_t)(r * SROW + q * 8) * 2;
            size_t gofs = (size_t)(row0 + r) * lda + k0 + q * 8;
            CP16(d, Ah + gofs);
            CP16(d + A_TILE * 2, Al + gofs);
        }
        // B: BN rows x 8 chunks, hi+lo
        for (int i = tid; i < BN * 8; i += 256) {
            int r = i >> 3, q = i & 7;
            uint32_t d = sb + (uint32_t)(2 * A_TILE + r * SROW + q * 8) * 2;
            size_t gofs = (size_t)(col0 + r) * ldb + k0 + q * 8;
            CP16(d, Bh + gofs);
            CP16(d + B_TILE * 2, Bl + gofs);
        }
    };

    const int NC = K / BK;
    stage(0, 0);
    CP_COMMIT();

    for (int c = 0; c < NC; c++) {
        if (c + 1 < NC) { stage((c + 1) & 1, c + 1); CP_COMMIT(); CP_WAIT1(); }
        else            { CP_WAIT0(); }
        __syncthreads();

        const bf16* sA = smem + (size_t)(c & 1) * STAGE;
        const bf16* sB = sA + 2 * A_TILE;

        #pragma unroll
        for (int ks = 0; ks < BK / 16; ks++) {
            const int kk = ks * 16;
            uint32_t ah[2][4], al[2][4];
            #pragma unroll
            for (int mt = 0; mt < 2; mt++) {
                const bf16* r0 = sA + (wrow0 + mt * 16 + g) * SROW + kk + t * 2;
                const bf16* r1 = r0 + 8 * SROW;
                ah[mt][0] = *(const uint32_t*)(r0);
                ah[mt][1] = *(const uint32_t*)(r1);
                ah[mt][2] = *(const uint32_t*)(r0 + 8);
                ah[mt][3] = *(const uint32_t*)(r1 + 8);
                al[mt][0] = *(const uint32_t*)(r0 + A_TILE);
                al[mt][1] = *(const uint32_t*)(r1 + A_TILE);
                al[mt][2] = *(const uint32_t*)(r0 + 8 + A_TILE);
                al[mt][3] = *(const uint32_t*)(r1 + 8 + A_TILE);
            }
            #pragma unroll
            for (int nt = 0; nt < NT; nt++) {
                const bf16* bn = sB + (wcol0 + nt * 8 + g) * SROW + kk + t * 2;
                uint32_t bh0 = *(const uint32_t*)(bn);
                uint32_t bh1 = *(const uint32_t*)(bn + 8);
                uint32_t bl0 = *(const uint32_t*)(bn + B_TILE);
                uint32_t bl1 = *(const uint32_t*)(bn + 8 + B_TILE);
                #pragma unroll
                for (int mt = 0; mt < 2; mt++) {
                    MMA16816(acc[mt][nt], ah[mt], bh0, bh1);   // hi*hi
                    MMA16816(acc[mt][nt], ah[mt], bl0, bl1);   // hi*lo
                    MMA16816(acc[mt][nt], al[mt], bh0, bh1);   // lo*hi
                }
            }
        }
        __syncthreads();
    }

    // ---- epilogue: fragment-direct stores ----
    #pragma unroll
    for (int mt = 0; mt < 2; mt++) {
        const int r = row0 + wrow0 + mt * 16 + g;
        #pragma unroll
        for (int nt = 0; nt < NT; nt++) {
            const int n = col0 + wcol0 + nt * 8 + t * 2;
            float v0 = acc[mt][nt][0] * alpha;
            float v1 = acc[mt][nt][1] * alpha;
            float v2 = acc[mt][nt][2] * alpha;
            float v3 = acc[mt][nt][3] * alpha;
            if (BIAS) { v0 += bias[n]; v1 += bias[n + 1]; v2 += bias[n]; v3 += bias[n + 1]; }
            if (RES) {
                v0 += resid[(size_t)r * ldres + n];
                v1 += resid[(size_t)r * ldres + n + 1];
                v2 += resid[(size_t)(r + 8) * ldres + n];
                v3 += resid[(size_t)(r + 8) * ldres + n + 1];
            }
            if (RELU) {
                v0 = fmaxf(v0, 0.f); v1 = fmaxf(v1, 0.f);
                v2 = fmaxf(v2, 0.f); v3 = fmaxf(v3, 0.f);
            }
            *(float2*)&C[(size_t)r * ldc + n]       = make_float2(v0, v1);
            *(float2*)&C[(size_t)(r + 8) * ldc + n] = make_float2(v2, v3);
        }
    }
}

// ---------------- LayerNorm ----------------
__global__ void ln_kernel(const float* __restrict__ x,
                          const float* __restrict__ gam,
                          const float* __restrict__ bet,
                          float* __restrict__ out) {
    int row = blockIdx.x;
    int t = threadIdx.x;
    const float4* xr = (const float4*)(x + (size_t)row * EMBED);
    float4 v = xr[t];
    float s  = v.x + v.y + v.z + v.w;
    float ss = v.x*v.x + v.y*v.y + v.z*v.z + v.w*v.w;
    #pragma unroll
    for (int o = 16; o; o >>= 1) {
        s  += __shfl_xor_sync(0xffffffffu, s,  o);
        ss += __shfl_xor_sync(0xffffffffu, ss, o);
    }
    __shared__ float shs[8], shs2[8];
    int w = t >> 5;
    if ((t & 31) == 0) { shs[w] = s; shs2[w] = ss; }
    __syncthreads();
    float tot = 0.f, tot2 = 0.f;
    #pragma unroll
    for (int i = 0; i < 8; i++) { tot += shs[i]; tot2 += shs2[i]; }
    float mu  = tot * (1.f / EMBED);
    float var = tot2 * (1.f / EMBED) - mu * mu;
    float rs  = rsqrtf(var + 1e-5f);
    float4 gv = ((const float4*)gam)[t];
    float4 bv = ((const float4*)bet)[t];
    float4 o;
    o.x = (v.x - mu) * rs * gv.x + bv.x;
    o.y = (v.y - mu) * rs * gv.y + bv.y;
    o.z = (v.z - mu) * rs * gv.z + bv.z;
    o.w = (v.w - mu) * rs * gv.w + bv.w;
    ((float4*)(out + (size_t)row * EMBED))[t] = o;
}

// ---------------- softmax -> bf16 split P ----------------
__global__ void softmax_split(const float* __restrict__ sc,
                              bf16* __restrict__ ph, bf16* __restrict__ pl) {
    size_t row = blockIdx.x;
    const float4* pr = (const float4*)(sc + row * (size_t)SEQ);
    int t = threadIdx.x;
    float4 a = pr[t];
    float4 b = pr[t + 256];
    float mx = fmaxf(fmaxf(fmaxf(a.x, a.y), fmaxf(a.z, a.w)),
                     fmaxf(fmaxf(b.x, b.y), fmaxf(b.z, b.w)));
    #pragma unroll
    for (int o = 16; o; o >>= 1) mx = fmaxf(mx, __shfl_xor_sync(0xffffffffu, mx, o));
    __shared__ float sh[8];
    int w = t >> 5;
    if ((t & 31) == 0) sh[w] = mx;
    __syncthreads();
    #pragma unroll
    for (int i = 0; i < 8; i++) mx = fmaxf(mx, sh[i]);
    __syncthreads();
    a.x = __expf(a.x - mx); a.y = __expf(a.y - mx);
    a.z = __expf(a.z - mx); a.w = __expf(a.w - mx);
    b.x = __expf(b.x - mx); b.y = __expf(b.y - mx);
    b.z = __expf(b.z - mx); b.w = __expf(b.w - mx);
    float s = a.x + a.y + a.z + a.w + b.x + b.y + b.z + b.w;
    #pragma unroll
    for (int o = 16; o; o >>= 1) s += __shfl_xor_sync(0xffffffffu, s, o);
    if ((t & 31) == 0) sh[w] = s;
    __syncthreads();
    float tot = 0.f;
    #pragma unroll
    for (int i = 0; i < 8; i++) tot += sh[i];
    float inv = 1.f / tot;
    float va[8] = {a.x*inv, a.y*inv, a.z*inv, a.w*inv,
                   b.x*inv, b.y*inv, b.z*inv, b.w*inv};
    size_t base = row * (size_t)SEQ;
    #pragma unroll
    for (int j = 0; j < 4; j++) {
        bf16 h, l; split1(va[j], h, l);
        ph[base + t*4 + j] = h;  pl[base + t*4 + j] = l;
    }
    #pragma unroll
    for (int j = 0; j < 4; j++) {
        bf16 h, l; split1(va[4 + j], h, l);
        ph[base + (t + 256)*4 + j] = h;  pl[base + (t + 256)*4 + j] = l;
    }
}

// ---------------- conversions ----------------
__global__ void conv_split4(const float* __restrict__ in,
                            bf16* __restrict__ hi, bf16* __restrict__ lo) {
    size_t i = (size_t)blockIdx.x * 256 + threadIdx.x;
    float4 v = ((const float4*)in)[i];
    bf16 h, l;
    split1(v.x, h, l); hi[i*4+0] = h; lo[i*4+0] = l;
    split1(v.y, h, l); hi[i*4+1] = h; lo[i*4+1] = l;
    split1(v.z, h, l); hi[i*4+2] = h; lo[i*4+2] = l;
    split1(v.w, h, l); hi[i*4+3] = h; lo[i*4+3] = l;
}

// qkv [b,s,3072] -> q[z,s,d]*0.125 and k[z,s,d], z = b*16+h
__global__ void conv_qk(const float* __restrict__ qkv,
                        bf16* __restrict__ qh, bf16* __restrict__ ql,
                        bf16* __restrict__ kh, bf16* __restrict__ kl) {
    size_t idx = (size_t)blockIdx.x * 256 + threadIdx.x;   // 32*2048*64
    int d = idx & 63;
    int s = (idx >> 6) & 2047;
    int z = idx >> 17;
    int zb = z >> 4, zh = z & 15;
    size_t src = ((size_t)(zb * 2048 + s)) * QKVN + zh * 64 + d;
    bf16 h, l;
    split1(qkv[src] * 0.125f, h, l);     qh[idx] = h; ql[idx] = l;
    split1(qkv[src + 1024], h, l);       kh[idx] = h; kl[idx] = l;
}

// qkv V -> vT[z,d,s]
__global__ void conv_vT(const float* __restrict__ qkv,
                        bf16* __restrict__ vh, bf16* __restrict__ vl) {
    size_t idx = (size_t)blockIdx.x * 256 + threadIdx.x;   // 32*64*2048
    int s = idx & 2047;
    int d = (idx >> 11) & 63;
    int z = idx >> 17;
    int zb = z >> 4, zh = z & 15;
    size_t src = ((size_t)(zb * 2048 + s)) * QKVN + 2048 + zh * 64 + d;
    bf16 h, l;
    split1(qkv[src], h, l);
    vh[idx] = h; vl[idx] = l;
}

// tiled transpose + split: out[n, k] = in[k, n], per-z batch
__global__ void conv_T(const float* __restrict__ in,
                       bf16* __restrict__ hi, bf16* __restrict__ lo,
                       int K, int N, long inz, long outz) {
    __shared__ float t[32][33];
    in += (size_t)blockIdx.z * inz;
    hi += (size_t)blockIdx.z * outz;
    lo += (size_t)blockIdx.z * outz;
    int n0 = blockIdx.x * 32, k0 = blockIdx.y * 32;
    int tx = threadIdx.x, ty = threadIdx.y;    // (32, 8)
    #pragma unroll
    for (int j = 0; j < 32; j += 8)
        t[ty + j][tx] = in[(size_t)(k0 + ty + j) * N + n0 + tx];
    __syncthreads();
    #pragma unroll
    for (int j = 0; j < 32; j += 8) {
        float v = t[tx][ty + j];
        bf16 h, l; split1(v, h, l);
        size_t o = (size_t)(n0 + ty + j) * K + k0 + tx;
        hi[o] = h; lo[o] = l;
    }
}

// ---------------- launch ----------------
extern "C" void kernel_launch(void* const* d_in, const int* in_sizes, int n_in,
                              void* d_out, int out_size) {
    const float* x    = (const float*)d_in[0];
    const float* Wqkv = (const float*)d_in[1];
    const float* bqkv = (const float*)d_in[2];
    const float* Wo   = (const float*)d_in[3];
    const float* bo   = (const float*)d_in[4];
    const float* W1   = (const float*)d_in[5];
    const float* b1   = (const float*)d_in[6];
    const float* W2   = (const float*)d_in[7];
    const float* b2   = (const float*)d_in[8];
    const float* g1   = (const float*)d_in[9];
    const float* be1  = (const float*)d_in[10];
    const float* g2   = (const float*)d_in[11];
    const float* be2  = (const float*)d_in[12];
    float* out = (float*)d_out;

    float *normed, *qkv, *scores, *attn, *x2, *normed2, *ff1;
    cudaGetSymbolAddress((void**)&normed,  g_normed);
    cudaGetSymbolAddress((void**)&qkv,     g_qkv);
    cudaGetSymbolAddress((void**)&scores,  g_scores);
    cudaGetSymbolAddress((void**)&attn,    g_attn);
    cudaGetSymbolAddress((void**)&x2,      g_x2);
    cudaGetSymbolAddress((void**)&normed2, g_normed2);
    cudaGetSymbolAddress((void**)&ff1,     g_ff1);

    bf16 *nrm_h,*nrm_l,*wqkvT_h,*wqkvT_l,*q_h,*q_l,*k_h,*k_l,*vT_h,*vT_l;
    bf16 *p_h,*p_l,*attn_h,*attn_l,*woT_h,*woT_l,*n2_h,*n2_l;
    bf16 *w1T_h,*w1T_l,*ff1_h,*ff1_l,*w2T_h,*w2T_l;
    cudaGetSymbolAddress((void**)&nrm_h,   g_nrm_h);   cudaGetSymbolAddress((void**)&nrm_l,   g_nrm_l);
    cudaGetSymbolAddress((void**)&wqkvT_h, g_wqkvT_h); cudaGetSymbolAddress((void**)&wqkvT_l, g_wqkvT_l);
    cudaGetSymbolAddress((void**)&q_h,     g_q_h);     cudaGetSymbolAddress((void**)&q_l,     g_q_l);
    cudaGetSymbolAddress((void**)&k_h,     g_k_h);     cudaGetSymbolAddress((void**)&k_l,     g_k_l);
    cudaGetSymbolAddress((void**)&vT_h,    g_vT_h);    cudaGetSymbolAddress((void**)&vT_l,    g_vT_l);
    cudaGetSymbolAddress((void**)&p_h,     g_p_h);     cudaGetSymbolAddress((void**)&p_l,     g_p_l);
    cudaGetSymbolAddress((void**)&attn_h,  g_attn_h);  cudaGetSymbolAddress((void**)&attn_l,  g_attn_l);
    cudaGetSymbolAddress((void**)&woT_h,   g_woT_h);   cudaGetSymbolAddress((void**)&woT_l,   g_woT_l);
    cudaGetSymbolAddress((void**)&n2_h,    g_n2_h);    cudaGetSymbolAddress((void**)&n2_l,    g_n2_l);
    cudaGetSymbolAddress((void**)&w1T_h,   g_w1T_h);   cudaGetSymbolAddress((void**)&w1T_l,   g_w1T_l);
    cudaGetSymbolAddress((void**)&ff1_h,   g_ff1_h);   cudaGetSymbolAddress((void**)&ff1_l,   g_ff1_l);
    cudaGetSymbolAddress((void**)&w2T_h,   g_w2T_h);   cudaGetSymbolAddress((void**)&w2T_l,   g_w2T_l);

    // dynamic smem: stage = (2*128 + 2*BN)*72 halves, double-buffered
    const int SM128 = 2 * (2*128 + 2*128) * 72 * 2;   // 147456
    const int SM64  = 2 * (2*128 + 2*64)  * 72 * 2;   // 110592
    cudaFuncSetAttribute(mma_gemm<128,true, false,false>, cudaFuncAttributeMaxDynamicSharedMemorySize, SM128);
    cudaFuncSetAttribute(mma_gemm<128,false,false,false>, cudaFuncAttributeMaxDynamicSharedMemorySize, SM128);
    cudaFuncSetAttribute(mma_gemm<64, false,false,false>, cudaFuncAttributeMaxDynamicSharedMemorySize, SM64);
    cudaFuncSetAttribute(mma_gemm<128,true, true, false>, cudaFuncAttributeMaxDynamicSharedMemorySize, SM128);
    cudaFuncSetAttribute(mma_gemm<128,true, false,true >, cudaFuncAttributeMaxDynamicSharedMemorySize, SM128);

    dim3 tblk(32, 8);

    // ---- weight conversions (transpose + split) ----
    conv_T<<<dim3(2, 32, 48), tblk>>>(Wqkv, wqkvT_h, wqkvT_l, EMBED, HD, 65536, 65536);
    conv_T<<<dim3(32, 32, 1), tblk>>>(Wo, woT_h, woT_l, EMBED, EMBED, 0, 0);
    conv_T<<<dim3(128,32, 1), tblk>>>(W1, w1T_h, w1T_l, EMBED, FF, 0, 0);
    conv_T<<<dim3(32,128, 1), tblk>>>(W2, w2T_h, w2T_l, FF, EMBED, 0, 0);

    // ---- LN1 + split ----
    ln_kernel<<<MTOK, 256>>>(x, g1, be1, normed);
    conv_split4<<<(MTOK*EMBED)/1024, 256>>>(normed, nrm_h, nrm_l);

    // ---- QKV projection: [4096,1024]@[1024,3072]^T(K-major) + bqkv ----
    mma_gemm<128,true,false,false><<<dim3(QKVN/128, MTOK/128, 1), 256, SM128>>>(
        nrm_h, nrm_l, wqkvT_h, wqkvT_l, bqkv, nullptr, qkv,
        EMBED, EMBED, EMBED, QKVN, 0, 0, 0, 0, 0, 1.f);

    // ---- split Q (pre-scaled 1/8), K, V^T ----
    conv_qk<<<(32*SEQ*HD)/256, 256>>>(qkv, q_h, q_l, k_h, k_l);
    conv_vT<<<(32*HD*SEQ)/256, 256>>>(qkv, vT_h, vT_l);

    // ---- scores = (Q/8) @ K^T ----
    mma_gemm<128,false,false,false><<<dim3(SEQ/128, SEQ/128, 32), 256, SM128>>>(
        q_h, q_l, k_h, k_l, nullptr, nullptr, scores,
        HD, HD, HD, SEQ, 0,
        (long)SEQ*HD, (long)SEQ*HD, (long)16*SEQ*SEQ, (long)SEQ*SEQ, 1.f);

    // ---- softmax -> P hi/lo ----
    softmax_split<<<32*SEQ, 256>>>(scores, p_h, p_l);

    // ---- attn = P @ V ----
    mma_gemm<64,false,false,false><<<dim3(1, SEQ/128, 32), 256, SM64>>>(
        p_h, p_l, vT_h, vT_l, nullptr, nullptr, attn,
        SEQ, SEQ, SEQ, EMBED, 0,
        (long)SEQ*SEQ, (long)HD*SEQ, (long)SEQ*EMBED, 64, 1.f);

    conv_split4<<<(MTOK*EMBED)/1024, 256>>>(attn, attn_h, attn_l);

    // ---- O projection + bias + residual -> x2 ----
    mma_gemm<128,true,true,false><<<dim3(EMBED/128, MTOK/128, 1), 256, SM128>>>(
        attn_h, attn_l, woT_h, woT_l, bo, x, x2,
        EMBED, EMBED, EMBED, EMBED, EMBED, 0, 0, 0, 0, 1.f);

    // ---- LN2 + split ----
    ln_kernel<<<MTOK, 256>>>(x2, g2, be2, normed2);
    conv_split4<<<(MTOK*EMBED)/1024, 256>>>(normed2, n2_h, n2_l);

    // ---- FF1 + bias + relu ----
    mma_gemm<128,true,false,true><<<dim3(FF/128, MTOK/128, 1), 256, SM128>>>(
        n2_h, n2_l, w1T_h, w1T_l, b1, nullptr, ff1,
        EMBED, EMBED, EMBED, FF, 0, 0, 0, 0, 0, 1.f);

    conv_split4<<<(MTOK*FF)/1024, 256>>>(ff1, ff1_h, ff1_l);

    // ---- FF2 + bias + residual -> out ----
    mma_gemm<128,true,true,false><<<dim3(EMBED/128, MTOK/128, 1), 256, SM128>>>(
        ff1_h, ff1_l, w2T_h, w2T_l, b2, x2, out,
        FF, FF, FF, EMBED, EMBED, 0, 0, 0, 0, 1.f);
}

// round 11
// speedup vs baseline: 3.0259x; 1.3808x over previous
#include <cuda_runtime.h>
#include <cuda_bf16.h>
#include <cstdint>
#include <math.h>

// ---------------- problem constants ----------------
#define BATCH 2
#define SEQ   2048
#define EMBED 1024
#define HEADS 16
#define HD    64
#define FF    4096
#define MTOK  (BATCH*SEQ)          // 4096
#define QKVN  (3*EMBED)            // 3072

typedef __nv_bfloat16 bf16;

// ---------------- device scratch ----------------
__device__ __align__(16) float g_qkv    [(size_t)MTOK*QKVN];
__device__ __align__(16) float g_x2     [(size_t)MTOK*EMBED];

__device__ __align__(16) bf16 g_nrm_h  [(size_t)MTOK*EMBED];
__device__ __align__(16) bf16 g_nrm_l  [(size_t)MTOK*EMBED];
__device__ __align__(16) bf16 g_wqkvT_h[(size_t)QKVN*EMBED];
__device__ __align__(16) bf16 g_wqkvT_l[(size_t)QKVN*EMBED];
__device__ __align__(16) bf16 g_q_h    [(size_t)BATCH*HEADS*SEQ*HD];
__device__ __align__(16) bf16 g_q_l    [(size_t)BATCH*HEADS*SEQ*HD];
__device__ __align__(16) bf16 g_k_h    [(size_t)BATCH*HEADS*SEQ*HD];
__device__ __align__(16) bf16 g_k_l    [(size_t)BATCH*HEADS*SEQ*HD];
__device__ __align__(16) bf16 g_vT_h   [(size_t)BATCH*HEADS*HD*SEQ];
__device__ __align__(16) bf16 g_vT_l   [(size_t)BATCH*HEADS*HD*SEQ];
__device__ __align__(16) bf16 g_attn_h [(size_t)MTOK*EMBED];
__device__ __align__(16) bf16 g_attn_l [(size_t)MTOK*EMBED];
__device__ __align__(16) bf16 g_woT_h  [(size_t)EMBED*EMBED];
__device__ __align__(16) bf16 g_woT_l  [(size_t)EMBED*EMBED];
__device__ __align__(16) bf16 g_n2_h   [(size_t)MTOK*EMBED];
__device__ __align__(16) bf16 g_n2_l   [(size_t)MTOK*EMBED];
__device__ __align__(16) bf16 g_w1T_h  [(size_t)FF*EMBED];
__device__ __align__(16) bf16 g_w1T_l  [(size_t)FF*EMBED];
__device__ __align__(16) bf16 g_ff1_h  [(size_t)MTOK*FF];
__device__ __align__(16) bf16 g_ff1_l  [(size_t)MTOK*FF];
__device__ __align__(16) bf16 g_w2T_h  [(size_t)EMBED*FF];
__device__ __align__(16) bf16 g_w2T_l  [(size_t)EMBED*FF];

// ---------------- PTX helpers (sm_80-level baseline only) ----------------
__device__ __forceinline__ uint32_t smem_u32(const void* p) {
    uint32_t a;
    asm("{ .reg .u64 t; cvta.to.shared.u64 t, %1; cvt.u32.u64 %0, t; }" : "=r"(a) : "l"(p));
    return a;
}
#define CP16(dst, src) \
    asm volatile("cp.async.cg.shared.global [%0], [%1], 16;" :: "r"(dst), "l"(src) : "memory")
#define CP_COMMIT() asm volatile("cp.async.commit_group;" ::: "memory")
#define CP_WAIT0()  asm volatile("cp.async.wait_group 0;" ::: "memory")
#define CP_WAIT1()  asm volatile("cp.async.wait_group 1;" ::: "memory")

#define MMA16816(d, a, b0, b1)                                               \
    asm volatile("mma.sync.aligned.m16n8k16.row.col.f32.bf16.bf16.f32 "      \
        "{%0,%1,%2,%3}, {%4,%5,%6,%7}, {%8,%9}, {%0,%1,%2,%3};"              \
        : "+f"((d)[0]), "+f"((d)[1]), "+f"((d)[2]), "+f"((d)[3])             \
        : "r"((a)[0]), "r"((a)[1]), "r"((a)[2]), "r"((a)[3]),                \
          "r"(b0), "r"(b1))

__device__ __forceinline__ float ex2f(float x) {
    float r;
    asm("ex2.approx.ftz.f32 %0, %1;" : "=f"(r) : "f"(x));
    return r;
}

// ---------------- split helpers ----------------
__device__ __forceinline__ void split1(float x, bf16& h, bf16& l) {
    h = __float2bfloat16(x);
    l = __float2bfloat16(x - __bfloat162float(h));
}
__device__ __forceinline__ uint32_t packbf(float a, float b) {
    __nv_bfloat162 p = __floats2bfloat162_rn(a, b);
    return *reinterpret_cast<uint32_t*>(&p);
}
__device__ __forceinline__ void split2(float a, float b, uint32_t& hp, uint32_t& lp) {
    hp = packbf(a, b);
    __nv_bfloat162 hh = *reinterpret_cast<__nv_bfloat162*>(&hp);
    lp = packbf(a - __bfloat162float(hh.x), b - __bfloat162float(hh.y));
}

// ---------------- HMMA bf16-split GEMM ----------------
// C = (Ah+Al)(Bh+Bl)^T (+bias)(+resid)(relu); SPLIT: write bf16 hi/lo.
template<bool BIAS, bool RES, bool RELU, bool SPLIT>
__global__ __launch_bounds__(256, 1)
void mma_gemm(const bf16* __restrict__ Ah, const bf16* __restrict__ Al,
              const bf16* __restrict__ Bh, const bf16* __restrict__ Bl,
              const float* __restrict__ bias, const float* __restrict__ resid,
              float* __restrict__ C, bf16* __restrict__ Ch, bf16* __restrict__ Cl,
              int K, int lda, int ldb, int ldc, int ldres)
{
    constexpr int BM = 128, BN = 128, BK = 64;
    constexpr int SROW   = BK + 8;
    constexpr int A_TILE = BM * SROW;
    constexpr int B_TILE = BN * SROW;
    constexpr int STAGE  = 2 * A_TILE + 2 * B_TILE;
    constexpr int NT     = 8;                   // warp covers 64 cols

    extern __shared__ __align__(16) bf16 smem[];
    const uint32_t sbase = smem_u32(smem);
    const int tid = threadIdx.x;

    const int row0 = blockIdx.y * BM;
    const int col0 = blockIdx.x * BN;

    const int wid = tid >> 5, lane = tid & 31;
    const int g = lane >> 2, t = lane & 3;
    const int wrow0 = (wid & 3) * 32;
    const int wcol0 = (wid >> 2) * 64;

    float acc[2][NT][4];
    #pragma unroll
    for (int mt = 0; mt < 2; mt++)
        #pragma unroll
        for (int nt = 0; nt < NT; nt++)
            #pragma unroll
            for (int i = 0; i < 4; i++) acc[mt][nt][i] = 0.f;

    auto stage = [&](int b, int c) {
        const int k0 = c * BK;
        const uint32_t sb = sbase + (uint32_t)b * STAGE * 2;
        for (int i = tid; i < BM * 8; i += 256) {
            int r = i >> 3, q = i & 7;
            uint32_t d = sb + (uint32_t)(r * SROW + q * 8) * 2;
            size_t gofs = (size_t)(row0 + r) * lda + k0 + q * 8;
            CP16(d, Ah + gofs);
            CP16(d + A_TILE * 2, Al + gofs);
        }
        for (int i = tid; i < BN * 8; i += 256) {
            int r = i >> 3, q = i & 7;
            uint32_t d = sb + (uint32_t)(2 * A_TILE + r * SROW + q * 8) * 2;
            size_t gofs = (size_t)(col0 + r) * ldb + k0 + q * 8;
            CP16(d, Bh + gofs);
            CP16(d + B_TILE * 2, Bl + gofs);
        }
    };

    const int NC = K / BK;
    stage(0, 0);
    CP_COMMIT();

    for (int c = 0; c < NC; c++) {
        if (c + 1 < NC) { stage((c + 1) & 1, c + 1); CP_COMMIT(); CP_WAIT1(); }
        else            { CP_WAIT0(); }
        __syncthreads();

        const bf16* sA = smem + (size_t)(c & 1) * STAGE;
        const bf16* sB = sA + 2 * A_TILE;

        #pragma unroll
        for (int ks = 0; ks < BK / 16; ks++) {
            const int kk = ks * 16;
            uint32_t ah[2][4], al[2][4];
            #pragma unroll
            for (int mt = 0; mt < 2; mt++) {
                const bf16* r0 = sA + (wrow0 + mt * 16 + g) * SROW + kk + t * 2;
                const bf16* r1 = r0 + 8 * SROW;
                ah[mt][0] = *(const uint32_t*)(r0);
                ah[mt][1] = *(const uint32_t*)(r1);
                ah[mt][2] = *(const uint32_t*)(r0 + 8);
                ah[mt][3] = *(const uint32_t*)(r1 + 8);
                al[mt][0] = *(const uint32_t*)(r0 + A_TILE);
                al[mt][1] = *(const uint32_t*)(r1 + A_TILE);
                al[mt][2] = *(const uint32_t*)(r0 + 8 + A_TILE);
                al[mt][3] = *(const uint32_t*)(r1 + 8 + A_TILE);
            }
            #pragma unroll
            for (int nt = 0; nt < NT; nt++) {
                const bf16* bn = sB + (wcol0 + nt * 8 + g) * SROW + kk + t * 2;
                uint32_t bh0 = *(const uint32_t*)(bn);
                uint32_t bh1 = *(const uint32_t*)(bn + 8);
                uint32_t bl0 = *(const uint32_t*)(bn + B_TILE);
                uint32_t bl1 = *(const uint32_t*)(bn + 8 + B_TILE);
                #pragma unroll
                for (int mt = 0; mt < 2; mt++) {
                    MMA16816(acc[mt][nt], ah[mt], bh0, bh1);
                    MMA16816(acc[mt][nt], ah[mt], bl0, bl1);
                    MMA16816(acc[mt][nt], al[mt], bh0, bh1);
                }
            }
        }
        __syncthreads();
    }

    #pragma unroll
    for (int mt = 0; mt < 2; mt++) {
        const int r = row0 + wrow0 + mt * 16 + g;
        #pragma unroll
        for (int nt = 0; nt < NT; nt++) {
            const int n = col0 + wcol0 + nt * 8 + t * 2;
            float v0 = acc[mt][nt][0];
            float v1 = acc[mt][nt][1];
            float v2 = acc[mt][nt][2];
            float v3 = acc[mt][nt][3];
            if (BIAS) { v0 += bias[n]; v1 += bias[n + 1]; v2 += bias[n]; v3 += bias[n + 1]; }
            if (RES) {
                v0 += resid[(size_t)r * ldres + n];
                v1 += resid[(size_t)r * ldres + n + 1];
                v2 += resid[(size_t)(r + 8) * ldres + n];
                v3 += resid[(size_t)(r + 8) * ldres + n + 1];
            }
            if (RELU) {
                v0 = fmaxf(v0, 0.f); v1 = fmaxf(v1, 0.f);
                v2 = fmaxf(v2, 0.f); v3 = fmaxf(v3, 0.f);
            }
            if (SPLIT) {
                uint32_t hp, lp;
                split2(v0, v1, hp, lp);
                *(uint32_t*)&Ch[(size_t)r * ldc + n] = hp;
                *(uint32_t*)&Cl[(size_t)r * ldc + n] = lp;
                split2(v2, v3, hp, lp);
                *(uint32_t*)&Ch[(size_t)(r + 8) * ldc + n] = hp;
                *(uint32_t*)&Cl[(size_t)(r + 8) * ldc + n] = lp;
            } else {
                *(float2*)&C[(size_t)r * ldc + n]       = make_float2(v0, v1);
                *(float2*)&C[(size_t)(r + 8) * ldc + n] = make_float2(v2, v3);
            }
        }
    }
}

// ---------------- Flash attention (per b,h; online softmax, log2 domain) ----------------
// Q pre-scaled by 0.125*log2(e). out written as bf16 hi/lo into [b*S, h*64+d].
__global__ __launch_bounds__(256, 1)
void flash_attn(const bf16* __restrict__ qh, const bf16* __restrict__ ql,
                const bf16* __restrict__ kh, const bf16* __restrict__ kl,
                const bf16* __restrict__ vh, const bf16* __restrict__ vl,
                bf16* __restrict__ outh, bf16* __restrict__ outl)
{
    constexpr int QL_OFF  = 128 * 72;            // 9216 halves
    constexpr int KST_OFF = 2 * 128 * 72;        // 18432
    constexpr int KSTAGE  = 2 * 128 * 72;        // hi+lo
    constexpr int VST_OFF = KST_OFF + 2 * KSTAGE; // 55296
    constexpr int VSTAGE  = 2 * 64 * 136;        // 17408

    extern __shared__ __align__(16) bf16 smem[];
    const uint32_t sb = smem_u32(smem);
    const int tid = threadIdx.x;
    const int z = blockIdx.y, zb = z >> 4, zh = z & 15;
    const int q0 = blockIdx.x * 128;

    const bf16* Qh = qh + (size_t)z * SEQ * HD;
    const bf16* Ql = ql + (size_t)z * SEQ * HD;
    const bf16* Kh = kh + (size_t)z * SEQ * HD;
    const bf16* Kl = kl + (size_t)z * SEQ * HD;
    const bf16* Vh = vh + (size_t)z * HD * SEQ;
    const bf16* Vl = vl + (size_t)z * HD * SEQ;

    auto stage_kv = [&](int b, int j) {
        const int s0 = j * 128;
        const uint32_t kb = sb + (uint32_t)(KST_OFF + b * KSTAGE) * 2;
        for (int i = tid; i < 1024; i += 256) {
            int r = i >> 3, c = i & 7;
            uint32_t d = kb + (uint32_t)(r * 72 + c * 8) * 2;
            size_t gofs = (size_t)(s0 + r) * HD + c * 8;
            CP16(d, Kh + gofs);
            CP16(d + 9216 * 2, Kl + gofs);
        }
        const uint32_t vb = sb + (uint32_t)(VST_OFF + b * VSTAGE) * 2;
        for (int i = tid; i < 1024; i += 256) {
            int r = i >> 4, c = i & 15;
            uint32_t d = vb + (uint32_t)(r * 136 + c * 8) * 2;
            size_t gofs = (size_t)r * SEQ + s0 + c * 8;
            CP16(d, Vh + gofs);
            CP16(d + 8704 * 2, Vl + gofs);
        }
    };

    // stage Q (once) + first K/V tile in one group
    for (int i = tid; i < 1024; i += 256) {
        int r = i >> 3, c = i & 7;
        uint32_t d = sb + (uint32_t)(r * 72 + c * 8) * 2;
        size_t gofs = (size_t)(q0 + r) * HD + c * 8;
        CP16(d, Qh + gofs);
        CP16(d + QL_OFF * 2, Ql + gofs);
    }
    stage_kv(0, 0);
    CP_COMMIT();

    const int wid = tid >> 5, lane = tid & 31;
    const int g = lane >> 2, t = lane & 3;
    const int wq = wid * 16;

    float o[8][4];
    #pragma unroll
    for (int nt = 0; nt < 8; nt++)
        #pragma unroll
        for (int i = 0; i < 4; i++) o[nt][i] = 0.f;
    float m0 = -1e30f, m1 = -1e30f, l0 = 0.f, l1 = 0.f;

    for (int j = 0; j < SEQ / 128; j++) {
        const int b = j & 1;
        if (j + 1 < SEQ / 128) { stage_kv(b ^ 1, j + 1); CP_COMMIT(); CP_WAIT1(); }
        else                   { CP_WAIT0(); }
        __syncthreads();

        const bf16* sK = smem + KST_OFF + b * KSTAGE;
        const bf16* sV = smem + VST_OFF + b * VSTAGE;

        // ---- S = Q @ K^T (log2 domain) ----
        float s[16][4];
        #pragma unroll
        for (int nt = 0; nt < 16; nt++)
            #pragma unroll
            for (int i = 0; i < 4; i++) s[nt][i] = 0.f;

        #pragma unroll
        for (int ks = 0; ks < 4; ks++) {
            const int kk = ks * 16;
            uint32_t ah[4], al[4];
            const bf16* r0 = smem + (wq + g) * 72 + kk + t * 2;
            const bf16* r1 = r0 + 8 * 72;
            ah[0] = *(const uint32_t*)(r0);
            ah[1] = *(const uint32_t*)(r1);
            ah[2] = *(const uint32_t*)(r0 + 8);
            ah[3] = *(const uint32_t*)(r1 + 8);
            al[0] = *(const uint32_t*)(r0 + QL_OFF);
            al[1] = *(const uint32_t*)(r1 + QL_OFF);
            al[2] = *(const uint32_t*)(r0 + 8 + QL_OFF);
            al[3] = *(const uint32_t*)(r1 + 8 + QL_OFF);
            #pragma unroll
            for (int nt = 0; nt < 16; nt++) {
                const bf16* bn = sK + (nt * 8 + g) * 72 + kk + t * 2;
                uint32_t bh0 = *(const uint32_t*)(bn);
                uint32_t bh1 = *(const uint32_t*)(bn + 8);
                uint32_t bl0 = *(const uint32_t*)(bn + 9216);
                uint32_t bl1 = *(const uint32_t*)(bn + 8 + 9216);
                MMA16816(s[nt], ah, bh0, bh1);
                MMA16816(s[nt], ah, bl0, bl1);
                MMA16816(s[nt], al, bh0, bh1);
            }
        }

        // ---- online softmax (rows g and g+8) ----
        float tm0 = -1e30f, tm1 = -1e30f;
        #pragma unroll
        for (int nt = 0; nt < 16; nt++) {
            tm0 = fmaxf(tm0, fmaxf(s[nt][0], s[nt][1]));
            tm1 = fmaxf(tm1, fmaxf(s[nt][2], s[nt][3]));
        }
        tm0 = fmaxf(tm0, __shfl_xor_sync(0xffffffffu, tm0, 1));
        tm0 = fmaxf(tm0, __shfl_xor_sync(0xffffffffu, tm0, 2));
        tm1 = fmaxf(tm1, __shfl_xor_sync(0xffffffffu, tm1, 1));
        tm1 = fmaxf(tm1, __shfl_xor_sync(0xffffffffu, tm1, 2));
        const float mn0 = fmaxf(m0, tm0), mn1 = fmaxf(m1, tm1);
        const float f0 = ex2f(m0 - mn0), f1 = ex2f(m1 - mn1);
        float sum0 = 0.f, sum1 = 0.f;
        #pragma unroll
        for (int nt = 0; nt < 16; nt++) {
            s[nt][0] = ex2f(s[nt][0] - mn0);
            s[nt][1] = ex2f(s[nt][1] - mn0);
            s[nt][2] = ex2f(s[nt][2] - mn1);
            s[nt][3] = ex2f(s[nt][3] - mn1);
            sum0 += s[nt][0] + s[nt][1];
            sum1 += s[nt][2] + s[nt][3];
        }
        sum0 += __shfl_xor_sync(0xffffffffu, sum0, 1);
        sum0 += __shfl_xor_sync(0xffffffffu, sum0, 2);
        sum1 += __shfl_xor_sync(0xffffffffu, sum1, 1);
        sum1 += __shfl_xor_sync(0xffffffffu, sum1, 2);
        l0 = l0 * f0 + sum0;  l1 = l1 * f1 + sum1;
        m0 = mn0;  m1 = mn1;
        #pragma unroll
        for (int nt = 0; nt < 8; nt++) {
            o[nt][0] *= f0; o[nt][1] *= f0;
            o[nt][2] *= f1; o[nt][3] *= f1;
        }

        // ---- O += P @ V (P split built from S fragments) ----
        #pragma unroll
        for (int kc = 0; kc < 8; kc++) {
            uint32_t ph[4], pl[4];
            split2(s[2*kc][0],   s[2*kc][1],   ph[0], pl[0]);
            split2(s[2*kc][2],   s[2*kc][3],   ph[1], pl[1]);
            split2(s[2*kc+1][0], s[2*kc+1][1], ph[2], pl[2]);
            split2(s[2*kc+1][2], s[2*kc+1][3], ph[3], pl[3]);
            #pragma unroll
            for (int nt = 0; nt < 8; nt++) {
                const bf16* bn = sV + (nt * 8 + g) * 136 + kc * 16 + t * 2;
                uint32_t bh0 = *(const uint32_t*)(bn);
                uint32_t bh1 = *(const uint32_t*)(bn + 8);
                uint32_t bl0 = *(const uint32_t*)(bn + 8704);
                uint32_t bl1 = *(const uint32_t*)(bn + 8 + 8704);
                MMA16816(o[nt], ph, bh0, bh1);
                MMA16816(o[nt], ph, bl0, bl1);
                MMA16816(o[nt], pl, bh0, bh1);
            }
        }
        __syncthreads();
    }

    // ---- normalize + write bf16 hi/lo ----
    const float i0 = 1.f / l0, i1 = 1.f / l1;
    const int row = zb * SEQ + q0 + wq + g;
    #pragma unroll
    for (int nt = 0; nt < 8; nt++) {
        const int col = zh * 64 + nt * 8 + t * 2;
        uint32_t hp, lp;
        split2(o[nt][0] * i0, o[nt][1] * i0, hp, lp);
        *(uint32_t*)&outh[(size_t)row * EMBED + col] = hp;
        *(uint32_t*)&outl[(size_t)row * EMBED + col] = lp;
        split2(o[nt][2] * i1, o[nt][3] * i1, hp, lp);
        *(uint32_t*)&outh[(size_t)(row + 8) * EMBED + col] = hp;
        *(uint32_t*)&outl[(size_t)(row + 8) * EMBED + col] = lp;
    }
}

// ---------------- LayerNorm -> bf16 hi/lo ----------------
__global__ void ln_split(const float* __restrict__ x,
                         const float* __restrict__ gam,
                         const float* __restrict__ bet,
                         bf16* __restrict__ hi, bf16* __restrict__ lo) {
    int row = blockIdx.x;
    int t = threadIdx.x;
    const float4* xr = (const float4*)(x + (size_t)row * EMBED);
    float4 v = xr[t];
    float s  = v.x + v.y + v.z + v.w;
    float ss = v.x*v.x + v.y*v.y + v.z*v.z + v.w*v.w;
    #pragma unroll
    for (int o = 16; o; o >>= 1) {
        s  += __shfl_xor_sync(0xffffffffu, s,  o);
        ss += __shfl_xor_sync(0xffffffffu, ss, o);
    }
    __shared__ float shs[8], shs2[8];
    int w = t >> 5;
    if ((t & 31) == 0) { shs[w] = s; shs2[w] = ss; }
    __syncthreads();
    float tot = 0.f, tot2 = 0.f;
    #pragma unroll
    for (int i = 0; i < 8; i++) { tot += shs[i]; tot2 += shs2[i]; }
    float mu  = tot * (1.f / EMBED);
    float var = tot2 * (1.f / EMBED) - mu * mu;
    float rs  = rsqrtf(var + 1e-5f);
    float4 gv = ((const float4*)gam)[t];
    float4 bv = ((const float4*)bet)[t];
    float o0 = (v.x - mu) * rs * gv.x + bv.x;
    float o1 = (v.y - mu) * rs * gv.y + bv.y;
    float o2 = (v.z - mu) * rs * gv.z + bv.z;
    float o3 = (v.w - mu) * rs * gv.w + bv.w;
    uint32_t hp, lp;
    size_t base = (size_t)row * EMBED + t * 4;
    split2(o0, o1, hp, lp);
    *(uint32_t*)&hi[base] = hp;  *(uint32_t*)&lo[base] = lp;
    split2(o2, o3, hp, lp);
    *(uint32_t*)&hi[base + 2] = hp;  *(uint32_t*)&lo[base + 2] = lp;
}

// ---------------- conversions ----------------
// qkv [b,s,3072] -> q[z,s,d]*(0.125*log2e) and k[z,s,d]
__global__ void conv_qk(const float* __restrict__ qkv,
                        bf16* __restrict__ qh, bf16* __restrict__ ql,
                        bf16* __restrict__ kh, bf16* __restrict__ kl) {
    const float SCL = 0.125f * 1.4426950408889634f;
    size_t idx = (size_t)blockIdx.x * 256 + threadIdx.x;
    int d = idx & 63;
    int s = (idx >> 6) & 2047;
    int z = idx >> 17;
    int zb = z >> 4, zh = z & 15;
    size_t src = ((size_t)(zb * 2048 + s)) * QKVN + zh * 64 + d;
    bf16 h, l;
    split1(qkv[src] * SCL, h, l);   qh[idx] = h; ql[idx] = l;
    split1(qkv[src + 1024], h, l);  kh[idx] = h; kl[idx] = l;
}

// qkv V -> vT[z,d,s]
__global__ void conv_vT(const float* __restrict__ qkv,
                        bf16* __restrict__ vh, bf16* __restrict__ vl) {
    size_t idx = (size_t)blockIdx.x * 256 + threadIdx.x;
    int s = idx & 2047;
    int d = (idx >> 11) & 63;
    int z = idx >> 17;
    int zb = z >> 4, zh = z & 15;
    size_t src = ((size_t)(zb * 2048 + s)) * QKVN + 2048 + zh * 64 + d;
    bf16 h, l;
    split1(qkv[src], h, l);
    vh[idx] = h; vl[idx] = l;
}

// tiled transpose + split
__global__ void conv_T(const float* __restrict__ in,
                       bf16* __restrict__ hi, bf16* __restrict__ lo,
                       int K, int N, long inz, long outz) {
    __shared__ float t[32][33];
    in += (size_t)blockIdx.z * inz;
    hi += (size_t)blockIdx.z * outz;
    lo += (size_t)blockIdx.z * outz;
    int n0 = blockIdx.x * 32, k0 = blockIdx.y * 32;
    int tx = threadIdx.x, ty = threadIdx.y;    // (32, 8)
    #pragma unroll
    for (int j = 0; j < 32; j += 8)
        t[ty + j][tx] = in[(size_t)(k0 + ty + j) * N + n0 + tx];
    __syncthreads();
    #pragma unroll
    for (int j = 0; j < 32; j += 8) {
        float v = t[tx][ty + j];
        bf16 h, l; split1(v, h, l);
        size_t o = (size_t)(n0 + ty + j) * K + k0 + tx;
        hi[o] = h; lo[o] = l;
    }
}

// ---------------- launch ----------------
extern "C" void kernel_launch(void* const* d_in, const int* in_sizes, int n_in,
                              void* d_out, int out_size) {
    const float* x    = (const float*)d_in[0];
    const float* Wqkv = (const float*)d_in[1];
    const float* bqkv = (const float*)d_in[2];
    const float* Wo   = (const float*)d_in[3];
    const float* bo   = (const float*)d_in[4];
    const float* W1   = (const float*)d_in[5];
    const float* b1   = (const float*)d_in[6];
    const float* W2   = (const float*)d_in[7];
    const float* b2   = (const float*)d_in[8];
    const float* g1   = (const float*)d_in[9];
    const float* be1  = (const float*)d_in[10];
    const float* g2   = (const float*)d_in[11];
    const float* be2  = (const float*)d_in[12];
    float* out = (float*)d_out;

    float *qkv, *x2;
    cudaGetSymbolAddress((void**)&qkv, g_qkv);
    cudaGetSymbolAddress((void**)&x2,  g_x2);

    bf16 *nrm_h,*nrm_l,*wqkvT_h,*wqkvT_l,*q_h,*q_l,*k_h,*k_l,*vT_h,*vT_l;
    bf16 *attn_h,*attn_l,*woT_h,*woT_l,*n2_h,*n2_l;
    bf16 *w1T_h,*w1T_l,*ff1_h,*ff1_l,*w2T_h,*w2T_l;
    cudaGetSymbolAddress((void**)&nrm_h,   g_nrm_h);   cudaGetSymbolAddress((void**)&nrm_l,   g_nrm_l);
    cudaGetSymbolAddress((void**)&wqkvT_h, g_wqkvT_h); cudaGetSymbolAddress((void**)&wqkvT_l, g_wqkvT_l);
    cudaGetSymbolAddress((void**)&q_h,     g_q_h);     cudaGetSymbolAddress((void**)&q_l,     g_q_l);
    cudaGetSymbolAddress((void**)&k_h,     g_k_h);     cudaGetSymbolAddress((void**)&k_l,     g_k_l);
    cudaGetSymbolAddress((void**)&vT_h,    g_vT_h);    cudaGetSymbolAddress((void**)&vT_l,    g_vT_l);
    cudaGetSymbolAddress((void**)&attn_h,  g_attn_h);  cudaGetSymbolAddress((void**)&attn_l,  g_attn_l);
    cudaGetSymbolAddress((void**)&woT_h,   g_woT_h);   cudaGetSymbolAddress((void**)&woT_l,   g_woT_l);
    cudaGetSymbolAddress((void**)&n2_h,    g_n2_h);    cudaGetSymbolAddress((void**)&n2_l,    g_n2_l);
    cudaGetSymbolAddress((void**)&w1T_h,   g_w1T_h);   cudaGetSymbolAddress((void**)&w1T_l,   g_w1T_l);
    cudaGetSymbolAddress((void**)&ff1_h,   g_ff1_h);   cudaGetSymbolAddress((void**)&ff1_l,   g_ff1_l);
    cudaGetSymbolAddress((void**)&w2T_h,   g_w2T_h);   cudaGetSymbolAddress((void**)&w2T_l,   g_w2T_l);

    const int SMGEMM = 2 * (2*128 + 2*128) * 72 * 2;   // 147456
    const int SMFA   = (2*128*72 + 2*(2*128*72) + 2*(2*64*136)) * 2;  // 180224
    cudaFuncSetAttribute(mma_gemm<true,false,false,false>, cudaFuncAttributeMaxDynamicSharedMemorySize, SMGEMM);
    cudaFuncSetAttribute(mma_gemm<true,true, false,false>, cudaFuncAttributeMaxDynamicSharedMemorySize, SMGEMM);
    cudaFuncSetAttribute(mma_gemm<true,false,true, true >, cudaFuncAttributeMaxDynamicSharedMemorySize, SMGEMM);
    cudaFuncSetAttribute(flash_attn, cudaFuncAttributeMaxDynamicSharedMemorySize, SMFA);

    dim3 tblk(32, 8);

    // weights: transpose + split
    conv_T<<<dim3(2, 32, 48), tblk>>>(Wqkv, wqkvT_h, wqkvT_l, EMBED, HD, 65536, 65536);
    conv_T<<<dim3(32, 32, 1), tblk>>>(Wo, woT_h, woT_l, EMBED, EMBED, 0, 0);
    conv_T<<<dim3(128,32, 1), tblk>>>(W1, w1T_h, w1T_l, EMBED, FF, 0, 0);
    conv_T<<<dim3(32,128, 1), tblk>>>(W2, w2T_h, w2T_l, FF, EMBED, 0, 0);

    // LN1 -> split
    ln_split<<<MTOK, 256>>>(x, g1, be1, nrm_h, nrm_l);

    // QKV projection -> fp32 qkv (+bias)
    mma_gemm<true,false,false,false><<<dim3(QKVN/128, MTOK/128), 256, SMGEMM>>>(
        nrm_h, nrm_l, wqkvT_h, wqkvT_l, bqkv, nullptr, qkv, nullptr, nullptr,
        EMBED, EMBED, EMBED, QKVN, 0);

    // split Q (scaled), K, V^T
    conv_qk<<<(32*SEQ*HD)/256, 256>>>(qkv, q_h, q_l, k_h, k_l);
    conv_vT<<<(32*HD*SEQ)/256, 256>>>(qkv, vT_h, vT_l);

    // fused attention -> attn hi/lo
    flash_attn<<<dim3(SEQ/128, 32), 256, SMFA>>>(
        q_h, q_l, k_h, k_l, vT_h, vT_l, attn_h, attn_l);

    // O projection + bias + residual(x) -> x2
    mma_gemm<true,true,false,false><<<dim3(EMBED/128, MTOK/128), 256, SMGEMM>>>(
        attn_h, attn_l, woT_h, woT_l, bo, x, x2, nullptr, nullptr,
        EMBED, EMBED, EMBED, EMBED, EMBED);

    // LN2 -> split
    ln_split<<<MTOK, 256>>>(x2, g2, be2, n2_h, n2_l);

    // FF1 + bias + relu -> ff1 hi/lo (split epilogue)
    mma_gemm<true,false,true,true><<<dim3(FF/128, MTOK/128), 256, SMGEMM>>>(
        n2_h, n2_l, w1T_h, w1T_l, b1, nullptr, nullptr, ff1_h, ff1_l,
        EMBED, EMBED, EMBED, FF, 0);

    // FF2 + bias + residual(x2) -> out
    mma_gemm<true,true,false,false><<<dim3(EMBED/128, MTOK/128), 256, SMGEMM>>>(
        ff1_h, ff1_l, w2T_h, w2T_l, b2, x2, out, nullptr, nullptr,
        FF, FF, FF, EMBED, EMBED);
}

// round 12
// speedup vs baseline: 3.0509x; 1.0083x over previous
#include <cuda_runtime.h>
#include <cuda_bf16.h>
#include <cstdint>
#include <math.h>

// ---------------- problem constants ----------------
#define BATCH 2
#define SEQ   2048
#define EMBED 1024
#define HEADS 16
#define HD    64
#define FF    4096
#define MTOK  (BATCH*SEQ)          // 4096
#define QKVN  (3*EMBED)            // 3072

typedef __nv_bfloat16 bf16;

// ---------------- device scratch ----------------
__device__ __align__(16) float g_qkv    [(size_t)MTOK*QKVN];
__device__ __align__(16) float g_x2     [(size_t)MTOK*EMBED];

__device__ __align__(16) bf16 g_nrm_h  [(size_t)MTOK*EMBED];
__device__ __align__(16) bf16 g_nrm_l  [(size_t)MTOK*EMBED];
__device__ __align__(16) bf16 g_wqkvT_h[(size_t)QKVN*EMBED];
__device__ __align__(16) bf16 g_wqkvT_l[(size_t)QKVN*EMBED];
__device__ __align__(16) bf16 g_q_h    [(size_t)BATCH*HEADS*SEQ*HD];
__device__ __align__(16) bf16 g_q_l    [(size_t)BATCH*HEADS*SEQ*HD];
__device__ __align__(16) bf16 g_k_h    [(size_t)BATCH*HEADS*SEQ*HD];
__device__ __align__(16) bf16 g_k_l    [(size_t)BATCH*HEADS*SEQ*HD];
__device__ __align__(16) bf16 g_vT_h   [(size_t)BATCH*HEADS*HD*SEQ];
__device__ __align__(16) bf16 g_vT_l   [(size_t)BATCH*HEADS*HD*SEQ];
__device__ __align__(16) bf16 g_attn_h [(size_t)MTOK*EMBED];
__device__ __align__(16) bf16 g_attn_l [(size_t)MTOK*EMBED];
__device__ __align__(16) bf16 g_woT_h  [(size_t)EMBED*EMBED];
__device__ __align__(16) bf16 g_woT_l  [(size_t)EMBED*EMBED];
__device__ __align__(16) bf16 g_n2_h   [(size_t)MTOK*EMBED];
__device__ __align__(16) bf16 g_n2_l   [(size_t)MTOK*EMBED];
__device__ __align__(16) bf16 g_w1T_h  [(size_t)FF*EMBED];
__device__ __align__(16) bf16 g_w1T_l  [(size_t)FF*EMBED];
__device__ __align__(16) bf16 g_ff1_h  [(size_t)MTOK*FF];
__device__ __align__(16) bf16 g_ff1_l  [(size_t)MTOK*FF];
__device__ __align__(16) bf16 g_w2T_h  [(size_t)EMBED*FF];
__device__ __align__(16) bf16 g_w2T_l  [(size_t)EMBED*FF];

// ---------------- PTX helpers (sm_80-level baseline only) ----------------
__device__ __forceinline__ uint32_t smem_u32(const void* p) {
    uint32_t a;
    asm("{ .reg .u64 t; cvta.to.shared.u64 t, %1; cvt.u32.u64 %0, t; }" : "=r"(a) : "l"(p));
    return a;
}
#define CP16(dst, src) \
    asm volatile("cp.async.cg.shared.global [%0], [%1], 16;" :: "r"(dst), "l"(src) : "memory")
#define CP_COMMIT() asm volatile("cp.async.commit_group;" ::: "memory")
#define CP_WAIT0()  asm volatile("cp.async.wait_group 0;" ::: "memory")
#define CP_WAIT1()  asm volatile("cp.async.wait_group 1;" ::: "memory")

#define MMA16816(d, a, b0, b1)                                               \
    asm volatile("mma.sync.aligned.m16n8k16.row.col.f32.bf16.bf16.f32 "      \
        "{%0,%1,%2,%3}, {%4,%5,%6,%7}, {%8,%9}, {%0,%1,%2,%3};"              \
        : "+f"((d)[0]), "+f"((d)[1]), "+f"((d)[2]), "+f"((d)[3])             \
        : "r"((a)[0]), "r"((a)[1]), "r"((a)[2]), "r"((a)[3]),                \
          "r"(b0), "r"(b1))

// ldmatrix x4 (sm_75+ baseline PTX)
#define LDSM4(r0, r1, r2, r3, addr)                                          \
    asm volatile("ldmatrix.sync.aligned.m8n8.x4.shared.b16 {%0,%1,%2,%3}, [%4];" \
        : "=r"(r0), "=r"(r1), "=r"(r2), "=r"(r3) : "r"(addr))

__device__ __forceinline__ float ex2f(float x) {
    float r;
    asm("ex2.approx.ftz.f32 %0, %1;" : "=f"(r) : "f"(x));
    return r;
}

// ---------------- split helpers ----------------
__device__ __forceinline__ void split1(float x, bf16& h, bf16& l) {
    h = __float2bfloat16(x);
    l = __float2bfloat16(x - __bfloat162float(h));
}
__device__ __forceinline__ uint32_t packbf(float a, float b) {
    __nv_bfloat162 p = __floats2bfloat162_rn(a, b);
    return *reinterpret_cast<uint32_t*>(&p);
}
__device__ __forceinline__ void split2(float a, float b, uint32_t& hp, uint32_t& lp) {
    hp = packbf(a, b);
    __nv_bfloat162 hh = *reinterpret_cast<__nv_bfloat162*>(&hp);
    lp = packbf(a - __bfloat162float(hh.x), b - __bfloat162float(hh.y));
}

// ldmatrix lane-address components.
// A x4 (row-major, regs a0..a3): row = m0 + ((lane>>3)&1)*8 + (lane&7), col = kk + (lane>>4)*8
// B x4 (K-major [n][k], regs {b0,b1} for 2 n8 tiles):
//   row = n0 + ((lane>>4)&1)*8 + (lane&7), col = kk + ((lane>>3)&1)*8
struct LaneAddr {
    int rA, cA, rB, cB;
    __device__ __forceinline__ LaneAddr(int lane) {
        rA = (lane & 7) + ((lane >> 3) & 1) * 8;
        cA = (lane >> 4) * 8;
        rB = (lane & 7) + ((lane >> 4) & 1) * 8;
        cB = ((lane >> 3) & 1) * 8;
    }
};

// ---------------- HMMA bf16-split GEMM ----------------
// C = (Ah+Al)(Bh+Bl)^T (+bias)(+resid)(relu); SPLIT: write bf16 hi/lo.
template<bool BIAS, bool RES, bool RELU, bool SPLIT>
__global__ __launch_bounds__(256, 1)
void mma_gemm(const bf16* __restrict__ Ah, const bf16* __restrict__ Al,
              const bf16* __restrict__ Bh, const bf16* __restrict__ Bl,
              const float* __restrict__ bias, const float* __restrict__ resid,
              float* __restrict__ C, bf16* __restrict__ Ch, bf16* __restrict__ Cl,
              int K, int lda, int ldb, int ldc, int ldres)
{
    constexpr int BM = 128, BN = 128, BK = 64;
    constexpr int SROW   = BK + 8;               // 72 halves (144 B: ldmatrix conflict-free)
    constexpr int A_TILE = BM * SROW;
    constexpr int B_TILE = BN * SROW;
    constexpr int STAGE  = 2 * A_TILE + 2 * B_TILE;
    constexpr int NT     = 8;

    extern __shared__ __align__(16) bf16 smem[];
    const uint32_t sbase = smem_u32(smem);
    const int tid = threadIdx.x;

    const int row0 = blockIdx.y * BM;
    const int col0 = blockIdx.x * BN;

    const int wid = tid >> 5, lane = tid & 31;
    const int g = lane >> 2, t = lane & 3;
    const int wrow0 = (wid & 3) * 32;
    const int wcol0 = (wid >> 2) * 64;
    const LaneAddr la(lane);

    float acc[2][NT][4];
    #pragma unroll
    for (int mt = 0; mt < 2; mt++)
        #pragma unroll
        for (int nt = 0; nt < NT; nt++)
            #pragma unroll
            for (int i = 0; i < 4; i++) acc[mt][nt][i] = 0.f;

    auto stage = [&](int b, int c) {
        const int k0 = c * BK;
        const uint32_t sb = sbase + (uint32_t)b * STAGE * 2;
        for (int i = tid; i < BM * 8; i += 256) {
            int r = i >> 3, q = i & 7;
            uint32_t d = sb + (uint32_t)(r * SROW + q * 8) * 2;
            size_t gofs = (size_t)(row0 + r) * lda + k0 + q * 8;
            CP16(d, Ah + gofs);
            CP16(d + A_TILE * 2, Al + gofs);
        }
        for (int i = tid; i < BN * 8; i += 256) {
            int r = i >> 3, q = i & 7;
            uint32_t d = sb + (uint32_t)(2 * A_TILE + r * SROW + q * 8) * 2;
            size_t gofs = (size_t)(col0 + r) * ldb + k0 + q * 8;
            CP16(d, Bh + gofs);
            CP16(d + B_TILE * 2, Bl + gofs);
        }
    };

    const int NC = K / BK;
    stage(0, 0);
    CP_COMMIT();

    for (int c = 0; c < NC; c++) {
        if (c + 1 < NC) { stage((c + 1) & 1, c + 1); CP_COMMIT(); CP_WAIT1(); }
        else            { CP_WAIT0(); }
        __syncthreads();

        const uint32_t bufb = sbase + (uint32_t)(c & 1) * STAGE * 2;
        const uint32_t aA = bufb + (uint32_t)((wrow0 + la.rA) * SROW + la.cA) * 2;
        const uint32_t aB = bufb + 2 * A_TILE * 2
                          + (uint32_t)((wcol0 + la.rB) * SROW + la.cB) * 2;

        #pragma unroll
        for (int ks = 0; ks < BK / 16; ks++) {
            const uint32_t kk2 = (uint32_t)ks * 32;     // 16 halves
            uint32_t ah[2][4], al[2][4];
            #pragma unroll
            for (int mt = 0; mt < 2; mt++) {
                uint32_t ab = aA + (uint32_t)mt * (16 * SROW * 2) + kk2;
                LDSM4(ah[mt][0], ah[mt][1], ah[mt][2], ah[mt][3], ab);
                LDSM4(al[mt][0], al[mt][1], al[mt][2], al[mt][3], ab + A_TILE * 2);
            }
            #pragma unroll
            for (int ntp = 0; ntp < 4; ntp++) {
                uint32_t bb = aB + (uint32_t)ntp * (16 * SROW * 2) + kk2;
                uint32_t h0a, h1a, h0b, h1b, l0a, l1a, l0b, l1b;
                LDSM4(h0a, h1a, h0b, h1b, bb);
                LDSM4(l0a, l1a, l0b, l1b, bb + B_TILE * 2);
                #pragma unroll
                for (int mt = 0; mt < 2; mt++) {
                    MMA16816(acc[mt][2*ntp],   ah[mt], h0a, h1a);
                    MMA16816(acc[mt][2*ntp],   ah[mt], l0a, l1a);
                    MMA16816(acc[mt][2*ntp],   al[mt], h0a, h1a);
                    MMA16816(acc[mt][2*ntp+1], ah[mt], h0b, h1b);
                    MMA16816(acc[mt][2*ntp+1], ah[mt], l0b, l1b);
                    MMA16816(acc[mt][2*ntp+1], al[mt], h0b, h1b);
                }
            }
        }
        __syncthreads();
    }

    #pragma unroll
    for (int mt = 0; mt < 2; mt++) {
        const int r = row0 + wrow0 + mt * 16 + g;
        #pragma unroll
        for (int nt = 0; nt < NT; nt++) {
            const int n = col0 + wcol0 + nt * 8 + t * 2;
            float v0 = acc[mt][nt][0];
            float v1 = acc[mt][nt][1];
            float v2 = acc[mt][nt][2];
            float v3 = acc[mt][nt][3];
            if (BIAS) { v0 += bias[n]; v1 += bias[n + 1]; v2 += bias[n]; v3 += bias[n + 1]; }
            if (RES) {
                v0 += resid[(size_t)r * ldres + n];
                v1 += resid[(size_t)r * ldres + n + 1];
                v2 += resid[(size_t)(r + 8) * ldres + n];
                v3 += resid[(size_t)(r + 8) * ldres + n + 1];
            }
            if (RELU) {
                v0 = fmaxf(v0, 0.f); v1 = fmaxf(v1, 0.f);
                v2 = fmaxf(v2, 0.f); v3 = fmaxf(v3, 0.f);
            }
            if (SPLIT) {
                uint32_t hp, lp;
                split2(v0, v1, hp, lp);
                *(uint32_t*)&Ch[(size_t)r * ldc + n] = hp;
                *(uint32_t*)&Cl[(size_t)r * ldc + n] = lp;
                split2(v2, v3, hp, lp);
                *(uint32_t*)&Ch[(size_t)(r + 8) * ldc + n] = hp;
                *(uint32_t*)&Cl[(size_t)(r + 8) * ldc + n] = lp;
            } else {
                *(float2*)&C[(size_t)r * ldc + n]       = make_float2(v0, v1);
                *(float2*)&C[(size_t)(r + 8) * ldc + n] = make_float2(v2, v3);
            }
        }
    }
}

// ---------------- Flash attention (per b,h; online softmax, log2 domain) ----------------
// Q pre-scaled by 0.125*log2(e). out written as bf16 hi/lo into [b*S, h*64+d].
__global__ __launch_bounds__(256, 1)
void flash_attn(const bf16* __restrict__ qh, const bf16* __restrict__ ql,
                const bf16* __restrict__ kh, const bf16* __restrict__ kl,
                const bf16* __restrict__ vh, const bf16* __restrict__ vl,
                bf16* __restrict__ outh, bf16* __restrict__ outl)
{
    constexpr int QL_OFF  = 128 * 72;             // 9216 halves
    constexpr int KST_OFF = 2 * 128 * 72;         // 18432
    constexpr int KSTAGE  = 2 * 128 * 72;
    constexpr int VST_OFF = KST_OFF + 2 * KSTAGE; // 55296
    constexpr int VSTAGE  = 2 * 64 * 136;         // 17408 (272 B rows: conflict-free)

    extern __shared__ __align__(16) bf16 smem[];
    const uint32_t sb = smem_u32(smem);
    const int tid = threadIdx.x;
    const int z = blockIdx.y, zb = z >> 4, zh = z & 15;
    const int q0 = blockIdx.x * 128;

    const bf16* Qh = qh + (size_t)z * SEQ * HD;
    const bf16* Ql = ql + (size_t)z * SEQ * HD;
    const bf16* Kh = kh + (size_t)z * SEQ * HD;
    const bf16* Kl = kl + (size_t)z * SEQ * HD;
    const bf16* Vh = vh + (size_t)z * HD * SEQ;
    const bf16* Vl = vl + (size_t)z * HD * SEQ;

    auto stage_kv = [&](int b, int j) {
        const int s0 = j * 128;
        const uint32_t kb = sb + (uint32_t)(KST_OFF + b * KSTAGE) * 2;
        for (int i = tid; i < 1024; i += 256) {
            int r = i >> 3, c = i & 7;
            uint32_t d = kb + (uint32_t)(r * 72 + c * 8) * 2;
            size_t gofs = (size_t)(s0 + r) * HD + c * 8;
            CP16(d, Kh + gofs);
            CP16(d + 9216 * 2, Kl + gofs);
        }
        const uint32_t vb = sb + (uint32_t)(VST_OFF + b * VSTAGE) * 2;
        for (int i = tid; i < 1024; i += 256) {
            int r = i >> 4, c = i & 15;
            uint32_t d = vb + (uint32_t)(r * 136 + c * 8) * 2;
            size_t gofs = (size_t)r * SEQ + s0 + c * 8;
            CP16(d, Vh + gofs);
            CP16(d + 8704 * 2, Vl + gofs);
        }
    };

    // stage Q (once) + first K/V tile in one group
    for (int i = tid; i < 1024; i += 256) {
        int r = i >> 3, c = i & 7;
        uint32_t d = sb + (uint32_t)(r * 72 + c * 8) * 2;
        size_t gofs = (size_t)(q0 + r) * HD + c * 8;
        CP16(d, Qh + gofs);
        CP16(d + QL_OFF * 2, Ql + gofs);
    }
    stage_kv(0, 0);
    CP_COMMIT();

    const int wid = tid >> 5, lane = tid & 31;
    const int g = lane >> 2, t = lane & 3;
    const int wq = wid * 16;
    const LaneAddr la(lane);

    float o[8][4];
    #pragma unroll
    for (int nt = 0; nt < 8; nt++)
        #pragma unroll
        for (int i = 0; i < 4; i++) o[nt][i] = 0.f;
    float m0 = -1e30f, m1 = -1e30f, l0 = 0.f, l1 = 0.f;

    const uint32_t aQ = sb + (uint32_t)((wq + la.rA) * 72 + la.cA) * 2;

    for (int j = 0; j < SEQ / 128; j++) {
        const int b = j & 1;
        if (j + 1 < SEQ / 128) { stage_kv(b ^ 1, j + 1); CP_COMMIT(); CP_WAIT1(); }
        else                   { CP_WAIT0(); }
        __syncthreads();

        const uint32_t kbase = sb + (uint32_t)(KST_OFF + b * KSTAGE) * 2
                             + (uint32_t)(la.rB * 72 + la.cB) * 2;
        const uint32_t vbase = sb + (uint32_t)(VST_OFF + b * VSTAGE) * 2
                             + (uint32_t)(la.rB * 136 + la.cB) * 2;

        // ---- S = Q @ K^T (log2 domain) ----
        float s[16][4];
        #pragma unroll
        for (int nt = 0; nt < 16; nt++)
            #pragma unroll
            for (int i = 0; i < 4; i++) s[nt][i] = 0.f;

        #pragma unroll
        for (int ks = 0; ks < 4; ks++) {
            const uint32_t kk2 = (uint32_t)ks * 32;
            uint32_t ah[4], al[4];
            LDSM4(ah[0], ah[1], ah[2], ah[3], aQ + kk2);
            LDSM4(al[0], al[1], al[2], al[3], aQ + kk2 + QL_OFF * 2);
            #pragma unroll
            for (int ntp = 0; ntp < 8; ntp++) {
                uint32_t bb = kbase + (uint32_t)ntp * (16 * 72 * 2) + kk2;
                uint32_t h0a, h1a, h0b, h1b, l0a, l1a, l0b, l1b;
                LDSM4(h0a, h1a, h0b, h1b, bb);
                LDSM4(l0a, l1a, l0b, l1b, bb + 9216 * 2);
                MMA16816(s[2*ntp],   ah, h0a, h1a);
                MMA16816(s[2*ntp],   ah, l0a, l1a);
                MMA16816(s[2*ntp],   al, h0a, h1a);
                MMA16816(s[2*ntp+1], ah, h0b, h1b);
                MMA16816(s[2*ntp+1], ah, l0b, l1b);
                MMA16816(s[2*ntp+1], al, h0b, h1b);
            }
        }

        // ---- online softmax (rows g and g+8) ----
        float tm0 = -1e30f, tm1 = -1e30f;
        #pragma unroll
        for (int nt = 0; nt < 16; nt++) {
            tm0 = fmaxf(tm0, fmaxf(s[nt][0], s[nt][1]));
            tm1 = fmaxf(tm1, fmaxf(s[nt][2], s[nt][3]));
        }
        tm0 = fmaxf(tm0, __shfl_xor_sync(0xffffffffu, tm0, 1));
        tm0 = fmaxf(tm0, __shfl_xor_sync(0xffffffffu, tm0, 2));
        tm1 = fmaxf(tm1, __shfl_xor_sync(0xffffffffu, tm1, 1));
        tm1 = fmaxf(tm1, __shfl_xor_sync(0xffffffffu, tm1, 2));
        const float mn0 = fmaxf(m0, tm0), mn1 = fmaxf(m1, tm1);
        const float f0 = ex2f(m0 - mn0), f1 = ex2f(m1 - mn1);
        float sum0 = 0.f, sum1 = 0.f;
        #pragma unroll
        for (int nt = 0; nt < 16; nt++) {
            s[nt][0] = ex2f(s[nt][0] - mn0);
            s[nt][1] = ex2f(s[nt][1] - mn0);
            s[nt][2] = ex2f(s[nt][2] - mn1);
            s[nt][3] = ex2f(s[nt][3] - mn1);
            sum0 += s[nt][0] + s[nt][1];
            sum1 += s[nt][2] + s[nt][3];
        }
        sum0 += __shfl_xor_sync(0xffffffffu, sum0, 1);
        sum0 += __shfl_xor_sync(0xffffffffu, sum0, 2);
        sum1 += __shfl_xor_sync(0xffffffffu, sum1, 1);
        sum1 += __shfl_xor_sync(0xffffffffu, sum1, 2);
        l0 = l0 * f0 + sum0;  l1 = l1 * f1 + sum1;
        m0 = mn0;  m1 = mn1;
        #pragma unroll
        for (int nt = 0; nt < 8; nt++) {
            o[nt][0] *= f0; o[nt][1] *= f0;
            o[nt][2] *= f1; o[nt][3] *= f1;
        }

        // ---- O += P @ V (P split built from S fragments) ----
        #pragma unroll
        for (int kc = 0; kc < 8; kc++) {
            uint32_t ph[4], pl[4];
            split2(s[2*kc][0],   s[2*kc][1],   ph[0], pl[0]);
            split2(s[2*kc][2],   s[2*kc][3],   ph[1], pl[1]);
            split2(s[2*kc+1][0], s[2*kc+1][1], ph[2], pl[2]);
            split2(s[2*kc+1][2], s[2*kc+1][3], ph[3], pl[3]);
            const uint32_t kk2 = (uint32_t)kc * 32;
            #pragma unroll
            for (int ntp = 0; ntp < 4; ntp++) {
                uint32_t bb = vbase + (uint32_t)ntp * (16 * 136 * 2) + kk2;
                uint32_t h0a, h1a, h0b, h1b, l0a, l1a, l0b, l1b;
                LDSM4(h0a, h1a, h0b, h1b, bb);
                LDSM4(l0a, l1a, l0b, l1b, bb + 8704 * 2);
                MMA16816(o[2*ntp],   ph, h0a, h1a);
                MMA16816(o[2*ntp],   ph, l0a, l1a);
                MMA16816(o[2*ntp],   pl, h0a, h1a);
                MMA16816(o[2*ntp+1], ph, h0b, h1b);
                MMA16816(o[2*ntp+1], ph, l0b, l1b);
                MMA16816(o[2*ntp+1], pl, h0b, h1b);
            }
        }
        __syncthreads();
    }

    // ---- normalize + write bf16 hi/lo ----
    const float i0 = 1.f / l0, i1 = 1.f / l1;
    const int row = zb * SEQ + q0 + wq + g;
    #pragma unroll
    for (int nt = 0; nt < 8; nt++) {
        const int col = zh * 64 + nt * 8 + t * 2;
        uint32_t hp, lp;
        split2(o[nt][0] * i0, o[nt][1] * i0, hp, lp);
        *(uint32_t*)&outh[(size_t)row * EMBED + col] = hp;
        *(uint32_t*)&outl[(size_t)row * EMBED + col] = lp;
        split2(o[nt][2] * i1, o[nt][3] * i1, hp, lp);
        *(uint32_t*)&outh[(size_t)(row + 8) * EMBED + col] = hp;
        *(uint32_t*)&outl[(size_t)(row + 8) * EMBED + col] = lp;
    }
}

// ---------------- LayerNorm -> bf16 hi/lo ----------------
__global__ void ln_split(const float* __restrict__ x,
                         const float* __restrict__ gam,
                         const float* __restrict__ bet,
                         bf16* __restrict__ hi, bf16* __restrict__ lo) {
    int row = blockIdx.x;
    int t = threadIdx.x;
    const float4* xr = (const float4*)(x + (size_t)row * EMBED);
    float4 v = xr[t];
    float s  = v.x + v.y + v.z + v.w;
    float ss = v.x*v.x + v.y*v.y + v.z*v.z + v.w*v.w;
    #pragma unroll
    for (int o = 16; o; o >>= 1) {
        s  += __shfl_xor_sync(0xffffffffu, s,  o);
        ss += __shfl_xor_sync(0xffffffffu, ss, o);
    }
    __shared__ float shs[8], shs2[8];
    int w = t >> 5;
    if ((t & 31) == 0) { shs[w] = s; shs2[w] = ss; }
    __syncthreads();
    float tot = 0.f, tot2 = 0.f;
    #pragma unroll
    for (int i = 0; i < 8; i++) { tot += shs[i]; tot2 += shs2[i]; }
    float mu  = tot * (1.f / EMBED);
    float var = tot2 * (1.f / EMBED) - mu * mu;
    float rs  = rsqrtf(var + 1e-5f);
    float4 gv = ((const float4*)gam)[t];
    float4 bv = ((const float4*)bet)[t];
    float o0 = (v.x - mu) * rs * gv.x + bv.x;
    float o1 = (v.y - mu) * rs * gv.y + bv.y;
    float o2 = (v.z - mu) * rs * gv.z + bv.z;
    float o3 = (v.w - mu) * rs * gv.w + bv.w;
    uint32_t hp, lp;
    size_t base = (size_t)row * EMBED + t * 4;
    split2(o0, o1, hp, lp);
    *(uint32_t*)&hi[base] = hp;  *(uint32_t*)&lo[base] = lp;
    split2(o2, o3, hp, lp);
    *(uint32_t*)&hi[base + 2] = hp;  *(uint32_t*)&lo[base + 2] = lp;
}

// ---------------- conversions ----------------
// qkv [b,s,3072] -> q[z,s,d]*(0.125*log2e) and k[z,s,d]
__global__ void conv_qk(const float* __restrict__ qkv,
                        bf16* __restrict__ qh, bf16* __restrict__ ql,
                        bf16* __restrict__ kh, bf16* __restrict__ kl) {
    const float SCL = 0.125f * 1.4426950408889634f;
    size_t idx = (size_t)blockIdx.x * 256 + threadIdx.x;
    int d = idx & 63;
    int s = (idx >> 6) & 2047;
    int z = idx >> 17;
    int zb = z >> 4, zh = z & 15;
    size_t src = ((size_t)(zb * 2048 + s)) * QKVN + zh * 64 + d;
    bf16 h, l;
    split1(qkv[src] * SCL, h, l);   qh[idx] = h; ql[idx] = l;
    split1(qkv[src + 1024], h, l);  kh[idx] = h; kl[idx] = l;
}

// qkv V -> vT[z,d,s]
__global__ void conv_vT(const float* __restrict__ qkv,
                        bf16* __restrict__ vh, bf16* __restrict__ vl) {
    size_t idx = (size_t)blockIdx.x * 256 + threadIdx.x;
    int s = idx & 2047;
    int d = (idx >> 11) & 63;
    int z = idx >> 17;
    int zb = z >> 4, zh = z & 15;
    size_t src = ((size_t)(zb * 2048 + s)) * QKVN + 2048 + zh * 64 + d;
    bf16 h, l;
    split1(qkv[src], h, l);
    vh[idx] = h; vl[idx] = l;
}

// tiled transpose + split
__global__ void conv_T(const float* __restrict__ in,
                       bf16* __restrict__ hi, bf16* __restrict__ lo,
                       int K, int N, long inz, long outz) {
    __shared__ float t[32][33];
    in += (size_t)blockIdx.z * inz;
    hi += (size_t)blockIdx.z * outz;
    lo += (size_t)blockIdx.z * outz;
    int n0 = blockIdx.x * 32, k0 = blockIdx.y * 32;
    int tx = threadIdx.x, ty = threadIdx.y;    // (32, 8)
    #pragma unroll
    for (int j = 0; j < 32; j += 8)
        t[ty + j][tx] = in[(size_t)(k0 + ty + j) * N + n0 + tx];
    __syncthreads();
    #pragma unroll
    for (int j = 0; j < 32; j += 8) {
        float v = t[tx][ty + j];
        bf16 h, l; split1(v, h, l);
        size_t o = (size_t)(n0 + ty + j) * K + k0 + tx;
        hi[o] = h; lo[o] = l;
    }
}

// ---------------- launch ----------------
extern "C" void kernel_launch(void* const* d_in, const int* in_sizes, int n_in,
                              void* d_out, int out_size) {
    const float* x    = (const float*)d_in[0];
    const float* Wqkv = (const float*)d_in[1];
    const float* bqkv = (const float*)d_in[2];
    const float* Wo   = (const float*)d_in[3];
    const float* bo   = (const float*)d_in[4];
    const float* W1   = (const float*)d_in[5];
    const float* b1   = (const float*)d_in[6];
    const float* W2   = (const float*)d_in[7];
    const float* b2   = (const float*)d_in[8];
    const float* g1   = (const float*)d_in[9];
    const float* be1  = (const float*)d_in[10];
    const float* g2   = (const float*)d_in[11];
    const float* be2  = (const float*)d_in[12];
    float* out = (float*)d_out;

    float *qkv, *x2;
    cudaGetSymbolAddress((void**)&qkv, g_qkv);
    cudaGetSymbolAddress((void**)&x2,  g_x2);

    bf16 *nrm_h,*nrm_l,*wqkvT_h,*wqkvT_l,*q_h,*q_l,*k_h,*k_l,*vT_h,*vT_l;
    bf16 *attn_h,*attn_l,*woT_h,*woT_l,*n2_h,*n2_l;
    bf16 *w1T_h,*w1T_l,*ff1_h,*ff1_l,*w2T_h,*w2T_l;
    cudaGetSymbolAddress((void**)&nrm_h,   g_nrm_h);   cudaGetSymbolAddress((void**)&nrm_l,   g_nrm_l);
    cudaGetSymbolAddress((void**)&wqkvT_h, g_wqkvT_h); cudaGetSymbolAddress((void**)&wqkvT_l, g_wqkvT_l);
    cudaGetSymbolAddress((void**)&q_h,     g_q_h);     cudaGetSymbolAddress((void**)&q_l,     g_q_l);
    cudaGetSymbolAddress((void**)&k_h,     g_k_h);     cudaGetSymbolAddress((void**)&k_l,     g_k_l);
    cudaGetSymbolAddress((void**)&vT_h,    g_vT_h);    cudaGetSymbolAddress((void**)&vT_l,    g_vT_l);
    cudaGetSymbolAddress((void**)&attn_h,  g_attn_h);  cudaGetSymbolAddress((void**)&attn_l,  g_attn_l);
    cudaGetSymbolAddress((void**)&woT_h,   g_woT_h);   cudaGetSymbolAddress((void**)&woT_l,   g_woT_l);
    cudaGetSymbolAddress((void**)&n2_h,    g_n2_h);    cudaGetSymbolAddress((void**)&n2_l,    g_n2_l);
    cudaGetSymbolAddress((void**)&w1T_h,   g_w1T_h);   cudaGetSymbolAddress((void**)&w1T_l,   g_w1T_l);
    cudaGetSymbolAddress((void**)&ff1_h,   g_ff1_h);   cudaGetSymbolAddress((void**)&ff1_l,   g_ff1_l);
    cudaGetSymbolAddress((void**)&w2T_h,   g_w2T_h);   cudaGetSymbolAddress((void**)&w2T_l,   g_w2T_l);

    const int SMGEMM = 2 * (2*128 + 2*128) * 72 * 2;   // 147456
    const int SMFA   = (2*128*72 + 2*(2*128*72) + 2*(2*64*136)) * 2;  // 180224
    cudaFuncSetAttribute(mma_gemm<true,false,false,false>, cudaFuncAttributeMaxDynamicSharedMemorySize, SMGEMM);
    cudaFuncSetAttribute(mma_gemm<true,true, false,false>, cudaFuncAttributeMaxDynamicSharedMemorySize, SMGEMM);
    cudaFuncSetAttribute(mma_gemm<true,false,true, true >, cudaFuncAttributeMaxDynamicSharedMemorySize, SMGEMM);
    cudaFuncSetAttribute(flash_attn, cudaFuncAttributeMaxDynamicSharedMemorySize, SMFA);

    dim3 tblk(32, 8);

    // weights: transpose + split
    conv_T<<<dim3(2, 32, 48), tblk>>>(Wqkv, wqkvT_h, wqkvT_l, EMBED, HD, 65536, 65536);
    conv_T<<<dim3(32, 32, 1), tblk>>>(Wo, woT_h, woT_l, EMBED, EMBED, 0, 0);
    conv_T<<<dim3(128,32, 1), tblk>>>(W1, w1T_h, w1T_l, EMBED, FF, 0, 0);
    conv_T<<<dim3(32,128, 1), tblk>>>(W2, w2T_h, w2T_l, FF, EMBED, 0, 0);

    // LN1 -> split
    ln_split<<<MTOK, 256>>>(x, g1, be1, nrm_h, nrm_l);

    // QKV projection -> fp32 qkv (+bias)
    mma_gemm<true,false,false,false><<<dim3(QKVN/128, MTOK/128), 256, SMGEMM>>>(
        nrm_h, nrm_l, wqkvT_h, wqkvT_l, bqkv, nullptr, qkv, nullptr, nullptr,
        EMBED, EMBED, EMBED, QKVN, 0);

    // split Q (scaled), K, V^T
    conv_qk<<<(32*SEQ*HD)/256, 256>>>(qkv, q_h, q_l, k_h, k_l);
    conv_vT<<<(32*HD*SEQ)/256, 256>>>(qkv, vT_h, vT_l);

    // fused attention -> attn hi/lo
    flash_attn<<<dim3(SEQ/128, 32), 256, SMFA>>>(
        q_h, q_l, k_h, k_l, vT_h, vT_l, attn_h, attn_l);

    // O projection + bias + residual(x) -> x2
    mma_gemm<true,true,false,false><<<dim3(EMBED/128, MTOK/128), 256, SMGEMM>>>(
        attn_h, attn_l, woT_h, woT_l, bo, x, x2, nullptr, nullptr,
        EMBED, EMBED, EMBED, EMBED, EMBED);

    // LN2 -> split
    ln_split<<<MTOK, 256>>>(x2, g2, be2, n2_h, n2_l);

    // FF1 + bias + relu -> ff1 hi/lo (split epilogue)
    mma_gemm<true,false,true,true><<<dim3(FF/128, MTOK/128), 256, SMGEMM>>>(
        n2_h, n2_l, w1T_h, w1T_l, b1, nullptr, nullptr, ff1_h, ff1_l,
        EMBED, EMBED, EMBED, FF, 0);

    // FF2 + bias + residual(x2) -> out
    mma_gemm<true,true,false,false><<<dim3(EMBED/128, MTOK/128), 256, SMGEMM>>>(
        ff1_h, ff1_l, w2T_h, w2T_l, b2, x2, out, nullptr, nullptr,
        FF, FF, FF, EMBED, EMBED);
}

// round 13
// speedup vs baseline: 3.0824x; 1.0103x over previous
#include <cuda_runtime.h>
#include <cuda_bf16.h>
#include <cstdint>
#include <math.h>

// ---------------- problem constants ----------------
#define BATCH 2
#define SEQ   2048
#define EMBED 1024
#define HEADS 16
#define HD    64
#define FF    4096
#define MTOK  (BATCH*SEQ)          // 4096
#define QKVN  (3*EMBED)            // 3072

typedef __nv_bfloat16 bf16;

// ---------------- device scratch ----------------
__device__ __align__(16) float g_qkv    [(size_t)MTOK*QKVN];
__device__ __align__(16) float g_x2     [(size_t)MTOK*EMBED];

__device__ __align__(16) bf16 g_nrm_h  [(size_t)MTOK*EMBED];
__device__ __align__(16) bf16 g_nrm_l  [(size_t)MTOK*EMBED];
__device__ __align__(16) bf16 g_wqkvT_h[(size_t)QKVN*EMBED];
__device__ __align__(16) bf16 g_wqkvT_l[(size_t)QKVN*EMBED];
__device__ __align__(16) bf16 g_q_h    [(size_t)BATCH*HEADS*SEQ*HD];
__device__ __align__(16) bf16 g_q_l    [(size_t)BATCH*HEADS*SEQ*HD];
__device__ __align__(16) bf16 g_k_h    [(size_t)BATCH*HEADS*SEQ*HD];
__device__ __align__(16) bf16 g_k_l    [(size_t)BATCH*HEADS*SEQ*HD];
__device__ __align__(16) bf16 g_vT_h   [(size_t)BATCH*HEADS*HD*SEQ];
__device__ __align__(16) bf16 g_vT_l   [(size_t)BATCH*HEADS*HD*SEQ];
__device__ __align__(16) bf16 g_attn_h [(size_t)MTOK*EMBED];
__device__ __align__(16) bf16 g_attn_l [(size_t)MTOK*EMBED];
__device__ __align__(16) bf16 g_woT_h  [(size_t)EMBED*EMBED];
__device__ __align__(16) bf16 g_woT_l  [(size_t)EMBED*EMBED];
__device__ __align__(16) bf16 g_n2_h   [(size_t)MTOK*EMBED];
__device__ __align__(16) bf16 g_n2_l   [(size_t)MTOK*EMBED];
__device__ __align__(16) bf16 g_w1T_h  [(size_t)FF*EMBED];
__device__ __align__(16) bf16 g_w1T_l  [(size_t)FF*EMBED];
__device__ __align__(16) bf16 g_ff1_h  [(size_t)MTOK*FF];
__device__ __align__(16) bf16 g_ff1_l  [(size_t)MTOK*FF];
__device__ __align__(16) bf16 g_w2T_h  [(size_t)EMBED*FF];
__device__ __align__(16) bf16 g_w2T_l  [(size_t)EMBED*FF];

// ---------------- PTX helpers (sm_80-level baseline only) ----------------
__device__ __forceinline__ uint32_t smem_u32(const void* p) {
    uint32_t a;
    asm("{ .reg .u64 t; cvta.to.shared.u64 t, %1; cvt.u32.u64 %0, t; }" : "=r"(a) : "l"(p));
    return a;
}
#define CP16(dst, src) \
    asm volatile("cp.async.cg.shared.global [%0], [%1], 16;" :: "r"(dst), "l"(src) : "memory")
#define CP_COMMIT() asm volatile("cp.async.commit_group;" ::: "memory")
#define CP_WAIT0()  asm volatile("cp.async.wait_group 0;" ::: "memory")
#define CP_WAIT1()  asm volatile("cp.async.wait_group 1;" ::: "memory")

#define MMA16816(d, a, b0, b1)                                               \
    asm volatile("mma.sync.aligned.m16n8k16.row.col.f32.bf16.bf16.f32 "      \
        "{%0,%1,%2,%3}, {%4,%5,%6,%7}, {%8,%9}, {%0,%1,%2,%3};"              \
        : "+f"((d)[0]), "+f"((d)[1]), "+f"((d)[2]), "+f"((d)[3])             \
        : "r"((a)[0]), "r"((a)[1]), "r"((a)[2]), "r"((a)[3]),                \
          "r"(b0), "r"(b1))

// ldmatrix x4 (sm_75+ baseline PTX)
#define LDSM4(r0, r1, r2, r3, addr)                                          \
    asm volatile("ldmatrix.sync.aligned.m8n8.x4.shared.b16 {%0,%1,%2,%3}, [%4];" \
        : "=r"(r0), "=r"(r1), "=r"(r2), "=r"(r3) : "r"(addr))

__device__ __forceinline__ float ex2f(float x) {
    float r;
    asm("ex2.approx.ftz.f32 %0, %1;" : "=f"(r) : "f"(x));
    return r;
}

// ---------------- split helpers ----------------
__device__ __forceinline__ void split1(float x, bf16& h, bf16& l) {
    h = __float2bfloat16(x);
    l = __float2bfloat16(x - __bfloat162float(h));
}
__device__ __forceinline__ uint32_t packbf(float a, float b) {
    __nv_bfloat162 p = __floats2bfloat162_rn(a, b);
    return *reinterpret_cast<uint32_t*>(&p);
}
__device__ __forceinline__ void split2(float a, float b, uint32_t& hp, uint32_t& lp) {
    hp = packbf(a, b);
    __nv_bfloat162 hh = *reinterpret_cast<__nv_bfloat162*>(&hp);
    lp = packbf(a - __bfloat162float(hh.x), b - __bfloat162float(hh.y));
}

// ldmatrix lane-address components.
struct LaneAddr {
    int rA, cA, rB, cB;
    __device__ __forceinline__ LaneAddr(int lane) {
        rA = (lane & 7) + ((lane >> 3) & 1) * 8;
        cA = (lane >> 4) * 8;
        rB = (lane & 7) + ((lane >> 4) & 1) * 8;
        cB = ((lane >> 3) & 1) * 8;
    }
};

// ---------------- HMMA bf16-split GEMM (BK=32, 2 CTAs/SM) ----------------
// C = (Ah+Al)(Bh+Bl)^T (+bias)(+resid)(relu); SPLIT: write bf16 hi/lo.
template<bool BIAS, bool RES, bool RELU, bool SPLIT>
__global__ __launch_bounds__(256, 2)
void mma_gemm(const bf16* __restrict__ Ah, const bf16* __restrict__ Al,
              const bf16* __restrict__ Bh, const bf16* __restrict__ Bl,
              const float* __restrict__ bias, const float* __restrict__ resid,
              float* __restrict__ C, bf16* __restrict__ Ch, bf16* __restrict__ Cl,
              int K, int lda, int ldb, int ldc, int ldres)
{
    constexpr int BM = 128, BN = 128, BK = 32;
    constexpr int SROW   = BK + 8;               // 40 halves (80 B rows: 5r mod 32 conflict-free)
    constexpr int A_TILE = BM * SROW;
    constexpr int B_TILE = BN * SROW;
    constexpr int STAGE  = 2 * A_TILE + 2 * B_TILE;   // 20480 halves
    constexpr int NT     = 8;

    extern __shared__ __align__(16) bf16 smem[];
    const uint32_t sbase = smem_u32(smem);
    const int tid = threadIdx.x;

    const int row0 = blockIdx.y * BM;
    const int col0 = blockIdx.x * BN;

    const int wid = tid >> 5, lane = tid & 31;
    const int g = lane >> 2, t = lane & 3;
    const int wrow0 = (wid & 3) * 32;
    const int wcol0 = (wid >> 2) * 64;
    const LaneAddr la(lane);

    float acc[2][NT][4];
    #pragma unroll
    for (int mt = 0; mt < 2; mt++)
        #pragma unroll
        for (int nt = 0; nt < NT; nt++)
            #pragma unroll
            for (int i = 0; i < 4; i++) acc[mt][nt][i] = 0.f;

    auto stage = [&](int b, int c) {
        const int k0 = c * BK;
        const uint32_t sb = sbase + (uint32_t)b * STAGE * 2;
        #pragma unroll
        for (int i = tid; i < BM * 4; i += 256) {
            int r = i >> 2, q = i & 3;
            uint32_t d = sb + (uint32_t)(r * SROW + q * 8) * 2;
            size_t gofs = (size_t)(row0 + r) * lda + k0 + q * 8;
            CP16(d, Ah + gofs);
            CP16(d + A_TILE * 2, Al + gofs);
        }
        #pragma unroll
        for (int i = tid; i < BN * 4; i += 256) {
            int r = i >> 2, q = i & 3;
            uint32_t d = sb + (uint32_t)(2 * A_TILE + r * SROW + q * 8) * 2;
            size_t gofs = (size_t)(col0 + r) * ldb + k0 + q * 8;
            CP16(d, Bh + gofs);
            CP16(d + B_TILE * 2, Bl + gofs);
        }
    };

    const int NC = K / BK;
    stage(0, 0);
    CP_COMMIT();

    for (int c = 0; c < NC; c++) {
        if (c + 1 < NC) { stage((c + 1) & 1, c + 1); CP_COMMIT(); CP_WAIT1(); }
        else            { CP_WAIT0(); }
        __syncthreads();

        const uint32_t bufb = sbase + (uint32_t)(c & 1) * STAGE * 2;
        const uint32_t aA = bufb + (uint32_t)((wrow0 + la.rA) * SROW + la.cA) * 2;
        const uint32_t aB = bufb + 2 * A_TILE * 2
                          + (uint32_t)((wcol0 + la.rB) * SROW + la.cB) * 2;

        #pragma unroll
        for (int ks = 0; ks < BK / 16; ks++) {
            const uint32_t kk2 = (uint32_t)ks * 32;     // 16 halves
            uint32_t ah[2][4], al[2][4];
            #pragma unroll
            for (int mt = 0; mt < 2; mt++) {
                uint32_t ab = aA + (uint32_t)mt * (16 * SROW * 2) + kk2;
                LDSM4(ah[mt][0], ah[mt][1], ah[mt][2], ah[mt][3], ab);
                LDSM4(al[mt][0], al[mt][1], al[mt][2], al[mt][3], ab + A_TILE * 2);
            }
            #pragma unroll
            for (int ntp = 0; ntp < 4; ntp++) {
                uint32_t bb = aB + (uint32_t)ntp * (16 * SROW * 2) + kk2;
                uint32_t h0a, h1a, h0b, h1b, l0a, l1a, l0b, l1b;
                LDSM4(h0a, h1a, h0b, h1b, bb);
                LDSM4(l0a, l1a, l0b, l1b, bb + B_TILE * 2);
                #pragma unroll
                for (int mt = 0; mt < 2; mt++) {
                    MMA16816(acc[mt][2*ntp],   ah[mt], h0a, h1a);
                    MMA16816(acc[mt][2*ntp],   ah[mt], l0a, l1a);
                    MMA16816(acc[mt][2*ntp],   al[mt], h0a, h1a);
                    MMA16816(acc[mt][2*ntp+1], ah[mt], h0b, h1b);
                    MMA16816(acc[mt][2*ntp+1], ah[mt], l0b, l1b);
                    MMA16816(acc[mt][2*ntp+1], al[mt], h0b, h1b);
                }
            }
        }
        __syncthreads();
    }

    #pragma unroll
    for (int mt = 0; mt < 2; mt++) {
        const int r = row0 + wrow0 + mt * 16 + g;
        #pragma unroll
        for (int nt = 0; nt < NT; nt++) {
            const int n = col0 + wcol0 + nt * 8 + t * 2;
            float v0 = acc[mt][nt][0];
            float v1 = acc[mt][nt][1];
            float v2 = acc[mt][nt][2];
            float v3 = acc[mt][nt][3];
            if (BIAS) { v0 += bias[n]; v1 += bias[n + 1]; v2 += bias[n]; v3 += bias[n + 1]; }
            if (RES) {
                v0 += resid[(size_t)r * ldres + n];
                v1 += resid[(size_t)r * ldres + n + 1];
                v2 += resid[(size_t)(r + 8) * ldres + n];
                v3 += resid[(size_t)(r + 8) * ldres + n + 1];
            }
            if (RELU) {
                v0 = fmaxf(v0, 0.f); v1 = fmaxf(v1, 0.f);
                v2 = fmaxf(v2, 0.f); v3 = fmaxf(v3, 0.f);
            }
            if (SPLIT) {
                uint32_t hp, lp;
                split2(v0, v1, hp, lp);
                *(uint32_t*)&Ch[(size_t)r * ldc + n] = hp;
                *(uint32_t*)&Cl[(size_t)r * ldc + n] = lp;
                split2(v2, v3, hp, lp);
                *(uint32_t*)&Ch[(size_t)(r + 8) * ldc + n] = hp;
                *(uint32_t*)&Cl[(size_t)(r + 8) * ldc + n] = lp;
            } else {
                *(float2*)&C[(size_t)r * ldc + n]       = make_float2(v0, v1);
                *(float2*)&C[(size_t)(r + 8) * ldc + n] = make_float2(v2, v3);
            }
        }
    }
}

// ---------------- Flash attention (per b,h; online softmax, log2 domain) ----------------
// Q pre-scaled by 0.125*log2(e). out written as bf16 hi/lo into [b*S, h*64+d].
__global__ __launch_bounds__(256, 1)
void flash_attn(const bf16* __restrict__ qh, const bf16* __restrict__ ql,
                const bf16* __restrict__ kh, const bf16* __restrict__ kl,
                const bf16* __restrict__ vh, const bf16* __restrict__ vl,
                bf16* __restrict__ outh, bf16* __restrict__ outl)
{
    constexpr int QL_OFF  = 128 * 72;             // 9216 halves
    constexpr int KST_OFF = 2 * 128 * 72;         // 18432
    constexpr int KSTAGE  = 2 * 128 * 72;
    constexpr int VST_OFF = KST_OFF + 2 * KSTAGE; // 55296
    constexpr int VSTAGE  = 2 * 64 * 136;         // 17408 (272 B rows: conflict-free)

    extern __shared__ __align__(16) bf16 smem[];
    const uint32_t sb = smem_u32(smem);
    const int tid = threadIdx.x;
    const int z = blockIdx.y, zb = z >> 4, zh = z & 15;
    const int q0 = blockIdx.x * 128;

    const bf16* Qh = qh + (size_t)z * SEQ * HD;
    const bf16* Ql = ql + (size_t)z * SEQ * HD;
    const bf16* Kh = kh + (size_t)z * SEQ * HD;
    const bf16* Kl = kl + (size_t)z * SEQ * HD;
    const bf16* Vh = vh + (size_t)z * HD * SEQ;
    const bf16* Vl = vl + (size_t)z * HD * SEQ;

    auto stage_kv = [&](int b, int j) {
        const int s0 = j * 128;
        const uint32_t kb = sb + (uint32_t)(KST_OFF + b * KSTAGE) * 2;
        for (int i = tid; i < 1024; i += 256) {
            int r = i >> 3, c = i & 7;
            uint32_t d = kb + (uint32_t)(r * 72 + c * 8) * 2;
            size_t gofs = (size_t)(s0 + r) * HD + c * 8;
            CP16(d, Kh + gofs);
            CP16(d + 9216 * 2, Kl + gofs);
        }
        const uint32_t vb = sb + (uint32_t)(VST_OFF + b * VSTAGE) * 2;
        for (int i = tid; i < 1024; i += 256) {
            int r = i >> 4, c = i & 15;
            uint32_t d = vb + (uint32_t)(r * 136 + c * 8) * 2;
            size_t gofs = (size_t)r * SEQ + s0 + c * 8;
            CP16(d, Vh + gofs);
            CP16(d + 8704 * 2, Vl + gofs);
        }
    };

    // stage Q (once) + first K/V tile in one group
    for (int i = tid; i < 1024; i += 256) {
        int r = i >> 3, c = i & 7;
        uint32_t d = sb + (uint32_t)(r * 72 + c * 8) * 2;
        size_t gofs = (size_t)(q0 + r) * HD + c * 8;
        CP16(d, Qh + gofs);
        CP16(d + QL_OFF * 2, Ql + gofs);
    }
    stage_kv(0, 0);
    CP_COMMIT();

    const int wid = tid >> 5, lane = tid & 31;
    const int g = lane >> 2, t = lane & 3;
    const int wq = wid * 16;
    const LaneAddr la(lane);

    float o[8][4];
    #pragma unroll
    for (int nt = 0; nt < 8; nt++)
        #pragma unroll
        for (int i = 0; i < 4; i++) o[nt][i] = 0.f;
    float m0 = -1e30f, m1 = -1e30f, l0 = 0.f, l1 = 0.f;

    const uint32_t aQ = sb + (uint32_t)((wq + la.rA) * 72 + la.cA) * 2;

    for (int j = 0; j < SEQ / 128; j++) {
        const int b = j & 1;
        if (j + 1 < SEQ / 128) { stage_kv(b ^ 1, j + 1); CP_COMMIT(); CP_WAIT1(); }
        else                   { CP_WAIT0(); }
        __syncthreads();

        const uint32_t kbase = sb + (uint32_t)(KST_OFF + b * KSTAGE) * 2
                             + (uint32_t)(la.rB * 72 + la.cB) * 2;
        const uint32_t vbase = sb + (uint32_t)(VST_OFF + b * VSTAGE) * 2
                             + (uint32_t)(la.rB * 136 + la.cB) * 2;

        // ---- S = Q @ K^T (log2 domain) ----
        float s[16][4];
        #pragma unroll
        for (int nt = 0; nt < 16; nt++)
            #pragma unroll
            for (int i = 0; i < 4; i++) s[nt][i] = 0.f;

        #pragma unroll
        for (int ks = 0; ks < 4; ks++) {
            const uint32_t kk2 = (uint32_t)ks * 32;
            uint32_t ah[4], al[4];
            LDSM4(ah[0], ah[1], ah[2], ah[3], aQ + kk2);
            LDSM4(al[0], al[1], al[2], al[3], aQ + kk2 + QL_OFF * 2);
            #pragma unroll
            for (int ntp = 0; ntp < 8; ntp++) {
                uint32_t bb = kbase + (uint32_t)ntp * (16 * 72 * 2) + kk2;
                uint32_t h0a, h1a, h0b, h1b, l0a, l1a, l0b, l1b;
                LDSM4(h0a, h1a, h0b, h1b, bb);
                LDSM4(l0a, l1a, l0b, l1b, bb + 9216 * 2);
                MMA16816(s[2*ntp],   ah, h0a, h1a);
                MMA16816(s[2*ntp],   ah, l0a, l1a);
                MMA16816(s[2*ntp],   al, h0a, h1a);
                MMA16816(s[2*ntp+1], ah, h0b, h1b);
                MMA16816(s[2*ntp+1], ah, l0b, l1b);
                MMA16816(s[2*ntp+1], al, h0b, h1b);
            }
        }

        // ---- online softmax (rows g and g+8) ----
        float tm0 = -1e30f, tm1 = -1e30f;
        #pragma unroll
        for (int nt = 0; nt < 16; nt++) {
            tm0 = fmaxf(tm0, fmaxf(s[nt][0], s[nt][1]));
            tm1 = fmaxf(tm1, fmaxf(s[nt][2], s[nt][3]));
        }
        tm0 = fmaxf(tm0, __shfl_xor_sync(0xffffffffu, tm0, 1));
        tm0 = fmaxf(tm0, __shfl_xor_sync(0xffffffffu, tm0, 2));
        tm1 = fmaxf(tm1, __shfl_xor_sync(0xffffffffu, tm1, 1));
        tm1 = fmaxf(tm1, __shfl_xor_sync(0xffffffffu, tm1, 2));
        const float mn0 = fmaxf(m0, tm0), mn1 = fmaxf(m1, tm1);
        const float f0 = ex2f(m0 - mn0), f1 = ex2f(m1 - mn1);
        float sum0 = 0.f, sum1 = 0.f;
        #pragma unroll
        for (int nt = 0; nt < 16; nt++) {
            s[nt][0] = ex2f(s[nt][0] - mn0);
            s[nt][1] = ex2f(s[nt][1] - mn0);
            s[nt][2] = ex2f(s[nt][2] - mn1);
            s[nt][3] = ex2f(s[nt][3] - mn1);
            sum0 += s[nt][0] + s[nt][1];
            sum1 += s[nt][2] + s[nt][3];
        }
        sum0 += __shfl_xor_sync(0xffffffffu, sum0, 1);
        sum0 += __shfl_xor_sync(0xffffffffu, sum0, 2);
        sum1 += __shfl_xor_sync(0xffffffffu, sum1, 1);
        sum1 += __shfl_xor_sync(0xffffffffu, sum1, 2);
        l0 = l0 * f0 + sum0;  l1 = l1 * f1 + sum1;
        m0 = mn0;  m1 = mn1;
        #pragma unroll
        for (int nt = 0; nt < 8; nt++) {
            o[nt][0] *= f0; o[nt][1] *= f0;
            o[nt][2] *= f1; o[nt][3] *= f1;
        }

        // ---- O += P @ V (P split built from S fragments) ----
        #pragma unroll
        for (int kc = 0; kc < 8; kc++) {
            uint32_t ph[4], pl[4];
            split2(s[2*kc][0],   s[2*kc][1],   ph[0], pl[0]);
            split2(s[2*kc][2],   s[2*kc][3],   ph[1], pl[1]);
            split2(s[2*kc+1][0], s[2*kc+1][1], ph[2], pl[2]);
            split2(s[2*kc+1][2], s[2*kc+1][3], ph[3], pl[3]);
            const uint32_t kk2 = (uint32_t)kc * 32;
            #pragma unroll
            for (int ntp = 0; ntp < 4; ntp++) {
                uint32_t bb = vbase + (uint32_t)ntp * (16 * 136 * 2) + kk2;
                uint32_t h0a, h1a, h0b, h1b, l0a, l1a, l0b, l1b;
                LDSM4(h0a, h1a, h0b, h1b, bb);
                LDSM4(l0a, l1a, l0b, l1b, bb + 8704 * 2);
                MMA16816(o[2*ntp],   ph, h0a, h1a);
                MMA16816(o[2*ntp],   ph, l0a, l1a);
                MMA16816(o[2*ntp],   pl, h0a, h1a);
                MMA16816(o[2*ntp+1], ph, h0b, h1b);
                MMA16816(o[2*ntp+1], ph, l0b, l1b);
                MMA16816(o[2*ntp+1], pl, h0b, h1b);
            }
        }
        __syncthreads();
    }

    // ---- normalize + write bf16 hi/lo ----
    const float i0 = 1.f / l0, i1 = 1.f / l1;
    const int row = zb * SEQ + q0 + wq + g;
    #pragma unroll
    for (int nt = 0; nt < 8; nt++) {
        const int col = zh * 64 + nt * 8 + t * 2;
        uint32_t hp, lp;
        split2(o[nt][0] * i0, o[nt][1] * i0, hp, lp);
        *(uint32_t*)&outh[(size_t)row * EMBED + col] = hp;
        *(uint32_t*)&outl[(size_t)row * EMBED + col] = lp;
        split2(o[nt][2] * i1, o[nt][3] * i1, hp, lp);
        *(uint32_t*)&outh[(size_t)(row + 8) * EMBED + col] = hp;
        *(uint32_t*)&outl[(size_t)(row + 8) * EMBED + col] = lp;
    }
}

// ---------------- LayerNorm -> bf16 hi/lo ----------------
__global__ void ln_split(const float* __restrict__ x,
                         const float* __restrict__ gam,
                         const float* __restrict__ bet,
                         bf16* __restrict__ hi, bf16* __restrict__ lo) {
    int row = blockIdx.x;
    int t = threadIdx.x;
    const float4* xr = (const float4*)(x + (size_t)row * EMBED);
    float4 v = xr[t];
    float s  = v.x + v.y + v.z + v.w;
    float ss = v.x*v.x + v.y*v.y + v.z*v.z + v.w*v.w;
    #pragma unroll
    for (int o = 16; o; o >>= 1) {
        s  += __shfl_xor_sync(0xffffffffu, s,  o);
        ss += __shfl_xor_sync(0xffffffffu, ss, o);
    }
    __shared__ float shs[8], shs2[8];
    int w = t >> 5;
    if ((t & 31) == 0) { shs[w] = s; shs2[w] = ss; }
    __syncthreads();
    float tot = 0.f, tot2 = 0.f;
    #pragma unroll
    for (int i = 0; i < 8; i++) { tot += shs[i]; tot2 += shs2[i]; }
    float mu  = tot * (1.f / EMBED);
    float var = tot2 * (1.f / EMBED) - mu * mu;
    float rs  = rsqrtf(var + 1e-5f);
    float4 gv = ((const float4*)gam)[t];
    float4 bv = ((const float4*)bet)[t];
    float o0 = (v.x - mu) * rs * gv.x + bv.x;
    float o1 = (v.y - mu) * rs * gv.y + bv.y;
    float o2 = (v.z - mu) * rs * gv.z + bv.z;
    float o3 = (v.w - mu) * rs * gv.w + bv.w;
    uint32_t hp, lp;
    size_t base = (size_t)row * EMBED + t * 4;
    split2(o0, o1, hp, lp);
    *(uint32_t*)&hi[base] = hp;  *(uint32_t*)&lo[base] = lp;
    split2(o2, o3, hp, lp);
    *(uint32_t*)&hi[base + 2] = hp;  *(uint32_t*)&lo[base + 2] = lp;
}

// ---------------- conversions ----------------
// qkv [b,s,3072] -> q[z,s,d]*(0.125*log2e) and k[z,s,d]
__global__ void conv_qk(const float* __restrict__ qkv,
                        bf16* __restrict__ qh, bf16* __restrict__ ql,
                        bf16* __restrict__ kh, bf16* __restrict__ kl) {
    const float SCL = 0.125f * 1.4426950408889634f;
    size_t idx = (size_t)blockIdx.x * 256 + threadIdx.x;
    int d = idx & 63;
    int s = (idx >> 6) & 2047;
    int z = idx >> 17;
    int zb = z >> 4, zh = z & 15;
    size_t src = ((size_t)(zb * 2048 + s)) * QKVN + zh * 64 + d;
    bf16 h, l;
    split1(qkv[src] * SCL, h, l);   qh[idx] = h; ql[idx] = l;
    split1(qkv[src + 1024], h, l);  kh[idx] = h; kl[idx] = l;
}

// qkv V -> vT[z,d,s]
__global__ void conv_vT(const float* __restrict__ qkv,
                        bf16* __restrict__ vh, bf16* __restrict__ vl) {
    size_t idx = (size_t)blockIdx.x * 256 + threadIdx.x;
    int s = idx & 2047;
    int d = (idx >> 11) & 63;
    int z = idx >> 17;
    int zb = z >> 4, zh = z & 15;
    size_t src = ((size_t)(zb * 2048 + s)) * QKVN + 2048 + zh * 64 + d;
    bf16 h, l;
    split1(qkv[src], h, l);
    vh[idx] = h; vl[idx] = l;
}

// tiled transpose + split
__global__ void conv_T(const float* __restrict__ in,
                       bf16* __restrict__ hi, bf16* __restrict__ lo,
                       int K, int N, long inz, long outz) {
    __shared__ float t[32][33];
    in += (size_t)blockIdx.z * inz;
    hi += (size_t)blockIdx.z * outz;
    lo += (size_t)blockIdx.z * outz;
    int n0 = blockIdx.x * 32, k0 = blockIdx.y * 32;
    int tx = threadIdx.x, ty = threadIdx.y;    // (32, 8)
    #pragma unroll
    for (int j = 0; j < 32; j += 8)
        t[ty + j][tx] = in[(size_t)(k0 + ty + j) * N + n0 + tx];
    __syncthreads();
    #pragma unroll
    for (int j = 0; j < 32; j += 8) {
        float v = t[tx][ty + j];
        bf16 h, l; split1(v, h, l);
        size_t o = (size_t)(n0 + ty + j) * K + k0 + tx;
        hi[o] = h; lo[o] = l;
    }
}

// ---------------- launch ----------------
extern "C" void kernel_launch(void* const* d_in, const int* in_sizes, int n_in,
                              void* d_out, int out_size) {
    const float* x    = (const float*)d_in[0];
    const float* Wqkv = (const float*)d_in[1];
    const float* bqkv = (const float*)d_in[2];
    const float* Wo   = (const float*)d_in[3];
    const float* bo   = (const float*)d_in[4];
    const float* W1   = (const float*)d_in[5];
    const float* b1   = (const float*)d_in[6];
    const float* W2   = (const float*)d_in[7];
    const float* b2   = (const float*)d_in[8];
    const float* g1   = (const float*)d_in[9];
    const float* be1  = (const float*)d_in[10];
    const float* g2   = (const float*)d_in[11];
    const float* be2  = (const float*)d_in[12];
    float* out = (float*)d_out;

    float *qkv, *x2;
    cudaGetSymbolAddress((void**)&qkv, g_qkv);
    cudaGetSymbolAddress((void**)&x2,  g_x2);

    bf16 *nrm_h,*nrm_l,*wqkvT_h,*wqkvT_l,*q_h,*q_l,*k_h,*k_l,*vT_h,*vT_l;
    bf16 *attn_h,*attn_l,*woT_h,*woT_l,*n2_h,*n2_l;
    bf16 *w1T_h,*w1T_l,*ff1_h,*ff1_l,*w2T_h,*w2T_l;
    cudaGetSymbolAddress((void**)&nrm_h,   g_nrm_h);   cudaGetSymbolAddress((void**)&nrm_l,   g_nrm_l);
    cudaGetSymbolAddress((void**)&wqkvT_h, g_wqkvT_h); cudaGetSymbolAddress((void**)&wqkvT_l, g_wqkvT_l);
    cudaGetSymbolAddress((void**)&q_h,     g_q_h);     cudaGetSymbolAddress((void**)&q_l,     g_q_l);
    cudaGetSymbolAddress((void**)&k_h,     g_k_h);     cudaGetSymbolAddress((void**)&k_l,     g_k_l);
    cudaGetSymbolAddress((void**)&vT_h,    g_vT_h);    cudaGetSymbolAddress((void**)&vT_l,    g_vT_l);
    cudaGetSymbolAddress((void**)&attn_h,  g_attn_h);  cudaGetSymbolAddress((void**)&attn_l,  g_attn_l);
    cudaGetSymbolAddress((void**)&woT_h,   g_woT_h);   cudaGetSymbolAddress((void**)&woT_l,   g_woT_l);
    cudaGetSymbolAddress((void**)&n2_h,    g_n2_h);    cudaGetSymbolAddress((void**)&n2_l,    g_n2_l);
    cudaGetSymbolAddress((void**)&w1T_h,   g_w1T_h);   cudaGetSymbolAddress((void**)&w1T_l,   g_w1T_l);
    cudaGetSymbolAddress((void**)&ff1_h,   g_ff1_h);   cudaGetSymbolAddress((void**)&ff1_l,   g_ff1_l);
    cudaGetSymbolAddress((void**)&w2T_h,   g_w2T_h);   cudaGetSymbolAddress((void**)&w2T_l,   g_w2T_l);

    const int SMGEMM = 2 * (2*128 + 2*128) * 40 * 2;   // 81920 (2 CTAs/SM)
    const int SMFA   = (2*128*72 + 2*(2*128*72) + 2*(2*64*136)) * 2;  // 180224
    cudaFuncSetAttribute(mma_gemm<true,false,false,false>, cudaFuncAttributeMaxDynamicSharedMemorySize, SMGEMM);
    cudaFuncSetAttribute(mma_gemm<true,true, false,false>, cudaFuncAttributeMaxDynamicSharedMemorySize, SMGEMM);
    cudaFuncSetAttribute(mma_gemm<true,false,true, true >, cudaFuncAttributeMaxDynamicSharedMemorySize, SMGEMM);
    cudaFuncSetAttribute(flash_attn, cudaFuncAttributeMaxDynamicSharedMemorySize, SMFA);

    dim3 tblk(32, 8);

    // weights: transpose + split
    conv_T<<<dim3(2, 32, 48), tblk>>>(Wqkv, wqkvT_h, wqkvT_l, EMBED, HD, 65536, 65536);
    conv_T<<<dim3(32, 32, 1), tblk>>>(Wo, woT_h, woT_l, EMBED, EMBED, 0, 0);
    conv_T<<<dim3(128,32, 1), tblk>>>(W1, w1T_h, w1T_l, EMBED, FF, 0, 0);
    conv_T<<<dim3(32,128, 1), tblk>>>(W2, w2T_h, w2T_l, FF, EMBED, 0, 0);

    // LN1 -> split
    ln_split<<<MTOK, 256>>>(x, g1, be1, nrm_h, nrm_l);

    // QKV projection -> fp32 qkv (+bias)
    mma_gemm<true,false,false,false><<<dim3(QKVN/128, MTOK/128), 256, SMGEMM>>>(
        nrm_h, nrm_l, wqkvT_h, wqkvT_l, bqkv, nullptr, qkv, nullptr, nullptr,
        EMBED, EMBED, EMBED, QKVN, 0);

    // split Q (scaled), K, V^T
    conv_qk<<<(32*SEQ*HD)/256, 256>>>(qkv, q_h, q_l, k_h, k_l);
    conv_vT<<<(32*HD*SEQ)/256, 256>>>(qkv, vT_h, vT_l);

    // fused attention -> attn hi/lo
    flash_attn<<<dim3(SEQ/128, 32), 256, SMFA>>>(
        q_h, q_l, k_h, k_l, vT_h, vT_l, attn_h, attn_l);

    // O projection + bias + residual(x) -> x2
    mma_gemm<true,true,false,false><<<dim3(EMBED/128, MTOK/128), 256, SMGEMM>>>(
        attn_h, attn_l, woT_h, woT_l, bo, x, x2, nullptr, nullptr,
        EMBED, EMBED, EMBED, EMBED, EMBED);

    // LN2 -> split
    ln_split<<<MTOK, 256>>>(x2, g2, be2, n2_h, n2_l);

    // FF1 + bias + relu -> ff1 hi/lo (split epilogue)
    mma_gemm<true,false,true,true><<<dim3(FF/128, MTOK/128), 256, SMGEMM>>>(
        n2_h, n2_l, w1T_h, w1T_l, b1, nullptr, nullptr, ff1_h, ff1_l,
        EMBED, EMBED, EMBED, FF, 0);

    // FF2 + bias + residual(x2) -> out
    mma_gemm<true,true,false,false><<<dim3(EMBED/128, MTOK/128), 256, SMGEMM>>>(
        ff1_h, ff1_l, w2T_h, w2T_l, b2, x2, out, nullptr, nullptr,
        FF, FF, FF, EMBED, EMBED);
}